// round 2
// baseline (speedup 1.0000x reference)
#include <cuda_runtime.h>
#include <math.h>

// Problem constants
#define BB 128      // batch
#define SS 512      // seq len
#define II 512      // input dim
#define HH 1024     // hidden dim
#define GG 4096     // 4*H (gates)

#define NB 128      // persistent blocks (<= SM count, all co-resident)
#define NT 256      // threads per block

// ---------------------------------------------------------------------------
// Device scratch (no cudaMalloc allowed -> __device__ globals)
// ---------------------------------------------------------------------------
__device__ float    g_xw[(size_t)SS * BB * GG];   // (s, b, 4H) : 1 GiB
__device__ float    g_hbuf[2][BB * HH];           // double-buffered hidden state
__device__ unsigned g_bar;                        // grid barrier counter

// ---------------------------------------------------------------------------
// init: zero h buffers + barrier counter (must reset every graph replay)
// ---------------------------------------------------------------------------
__global__ void lstm_init() {
    int idx = blockIdx.x * blockDim.x + threadIdx.x; // 131072 threads
    g_hbuf[0][idx] = 0.0f;
    g_hbuf[1][idx] = 0.0f;
    if (idx == 0) g_bar = 0u;
}

// ---------------------------------------------------------------------------
// GEMM 1: xW = x @ W + bias
//   A = x viewed as (M=65536, K=512) row-major, m = b*SS + s
//   B = W (512, 4096) row-major
//   C stored to g_xw[(s*BB + b)*GG + n]
// Tiling: BM=BN=128, BK=16, 8x8 micro-tile, 256 threads. Grid (512, 32).
// ---------------------------------------------------------------------------
__global__ __launch_bounds__(256) void gemm_xw(
    const float* __restrict__ x, const float* __restrict__ W,
    const float* __restrict__ bias)
{
    const int BM = 128, BN = 128, BK = 16;
    __shared__ float As[BK][BM];
    __shared__ float Bs[BK][BN];

    const int m0 = blockIdx.x * BM;
    const int n0 = blockIdx.y * BN;
    const int tid = threadIdx.x;

    const int tm = (tid >> 4) * 8;
    const int tn = (tid & 15) * 8;

    float acc[8][8];
#pragma unroll
    for (int i = 0; i < 8; i++)
#pragma unroll
        for (int j = 0; j < 8; j++) acc[i][j] = 0.0f;

    for (int k0 = 0; k0 < II; k0 += BK) {
#pragma unroll
        for (int i = 0; i < 2; i++) {
            int f4 = i * 256 + tid;
            int r = f4 >> 2;
            int c4 = f4 & 3;
            float4 v = *(const float4*)&x[(size_t)(m0 + r) * II + k0 + c4 * 4];
            As[c4 * 4 + 0][r] = v.x;
            As[c4 * 4 + 1][r] = v.y;
            As[c4 * 4 + 2][r] = v.z;
            As[c4 * 4 + 3][r] = v.w;
        }
#pragma unroll
        for (int i = 0; i < 2; i++) {
            int f4 = i * 256 + tid;
            int r = f4 >> 5;
            int c4 = f4 & 31;
            float4 v = *(const float4*)&W[(size_t)(k0 + r) * GG + n0 + c4 * 4];
            *(float4*)&Bs[r][c4 * 4] = v;
        }
        __syncthreads();

#pragma unroll
        for (int k = 0; k < BK; k++) {
            float4 a0 = *(const float4*)&As[k][tm];
            float4 a1 = *(const float4*)&As[k][tm + 4];
            float4 b0 = *(const float4*)&Bs[k][tn];
            float4 b1 = *(const float4*)&Bs[k][tn + 4];
            float a[8] = {a0.x, a0.y, a0.z, a0.w, a1.x, a1.y, a1.z, a1.w};
            float b[8] = {b0.x, b0.y, b0.z, b0.w, b1.x, b1.y, b1.z, b1.w};
#pragma unroll
            for (int i = 0; i < 8; i++)
#pragma unroll
                for (int j = 0; j < 8; j++) acc[i][j] = fmaf(a[i], b[j], acc[i][j]);
        }
        __syncthreads();
    }

    float bv[8];
#pragma unroll
    for (int j = 0; j < 8; j++) bv[j] = bias[n0 + tn + j];

#pragma unroll
    for (int i = 0; i < 8; i++) {
        int m = m0 + tm + i;
        int b = m >> 9;          // / SS
        int s = m & 511;         // % SS
        size_t dst = ((size_t)s * BB + b) * GG + n0 + tn;
        float4 v0 = make_float4(acc[i][0] + bv[0], acc[i][1] + bv[1],
                                acc[i][2] + bv[2], acc[i][3] + bv[3]);
        float4 v1 = make_float4(acc[i][4] + bv[4], acc[i][5] + bv[5],
                                acc[i][6] + bv[6], acc[i][7] + bv[7]);
        *(float4*)&g_xw[dst]     = v0;
        *(float4*)&g_xw[dst + 4] = v1;
    }
}

// ---------------------------------------------------------------------------
// Persistent recurrence kernel: 128 blocks, one grid barrier per step.
// Block bx owns hidden units [bx*8, bx*8+8) -> 32 gate columns
// (4 gates x 8), full batch M=128, K=1024.
// c-state and the output accumulator live in registers for the whole kernel.
// ---------------------------------------------------------------------------
__device__ __forceinline__ float sigm(float v) {
    return 1.0f / (1.0f + __expf(-v));
}

__global__ __launch_bounds__(NT, 1) void lstm_persist(
    const float* __restrict__ U, float* __restrict__ out)
{
    __shared__ float As[32][132];   // h tile, transposed, padded
    __shared__ float Bs[32][36];    // U tile, padded
    __shared__ float S[128][33];    // staged gate pre-activations

    const int tid = threadIdx.x;
    const int hb  = blockIdx.x * 8;       // hidden-unit base for this block

    // GEMM micro-tile mapping: 32 x 8 thread grid, 4x4 outputs each
    const int tm = (tid >> 3) * 4;        // 0..124
    const int tn = (tid & 7) * 4;         // 0..28

    // Update mapping: each thread owns batch row um, hidden units hb+uh..+3
    const int um = tid >> 1;              // 0..127
    const int uh = (tid & 1) * 4;         // 0 or 4

    float c_reg[4] = {0.f, 0.f, 0.f, 0.f};
    float oacc[4]  = {0.f, 0.f, 0.f, 0.f};

    for (int t = 0; t < SS; t++) {
        const float* hcur = g_hbuf[t & 1];

        float acc[4][4];
#pragma unroll
        for (int i = 0; i < 4; i++)
#pragma unroll
            for (int j = 0; j < 4; j++) acc[i][j] = 0.0f;

        for (int k0 = 0; k0 < HH; k0 += 32) {
            // A tile: h[0..127][k0..k0+31], transposed into As (L2 loads)
#pragma unroll
            for (int i = 0; i < 4; i++) {
                int f4 = i * 256 + tid;
                int r  = f4 >> 3;          // 0..127
                int c4 = f4 & 7;           // 0..7
                const float4* src =
                    (const float4*)&hcur[(size_t)r * HH + k0 + c4 * 4];
                float4 v = __ldcg(src);    // bypass L1: h is cross-SM mutable
                As[c4 * 4 + 0][r] = v.x;
                As[c4 * 4 + 1][r] = v.y;
                As[c4 * 4 + 2][r] = v.z;
                As[c4 * 4 + 3][r] = v.w;
            }
            // B tile: U[k0..k0+31][4 gate groups x 8 cols]
            {
                int r = tid >> 3;          // 0..31
                int c = tid & 7;           // 0..7
#pragma unroll
                for (int g = 0; g < 4; g++)
                    Bs[r][g * 8 + c] =
                        U[(size_t)(k0 + r) * GG + g * HH + hb + c];
            }
            __syncthreads();

#pragma unroll
            for (int k = 0; k < 32; k++) {
                float4 a = *(const float4*)&As[k][tm];
                float4 b = *(const float4*)&Bs[k][tn];
                float av[4] = {a.x, a.y, a.z, a.w};
                float bv[4] = {b.x, b.y, b.z, b.w};
#pragma unroll
                for (int i = 0; i < 4; i++)
#pragma unroll
                    for (int j = 0; j < 4; j++)
                        acc[i][j] = fmaf(av[i], bv[j], acc[i][j]);
            }
            __syncthreads();
        }

        // Stage gate pre-activations (recurrent part) into smem
#pragma unroll
        for (int i = 0; i < 4; i++)
#pragma unroll
            for (int j = 0; j < 4; j++)
                S[tm + i][tn + j] = acc[i][j];
        __syncthreads();

        // Fused cell update: gates = S + xw_t ; c,h update; out accumulate
        float* hnext = g_hbuf[(t + 1) & 1];
        float hv[4];
        {
            size_t xbase = ((size_t)t * BB + um) * GG + hb + uh;
#pragma unroll
            for (int j = 0; j < 4; j++) {
                int hh = uh + j;
                float gf = S[um][hh]      + g_xw[xbase + j];
                float gi = S[um][8 + hh]  + g_xw[xbase + j + HH];
                float gg = S[um][16 + hh] + g_xw[xbase + j + 2 * HH];
                float go = S[um][24 + hh] + g_xw[xbase + j + 3 * HH];

                float f  = sigm(gf);
                float in = sigm(gi);
                float g  = tanhf(gg);
                float o  = sigm(go);

                float c  = fmaf(f, c_reg[j], in * g);
                c_reg[j] = c;
                float h  = o * tanhf(c);
                hv[j]    = h;
                oacc[j] += h;
            }
        }
        *(float4*)&hnext[(size_t)um * HH + hb + uh] =
            make_float4(hv[0], hv[1], hv[2], hv[3]);

        // ---- grid barrier (release: fence+arrive, acquire: spin+fence) ----
        __threadfence();            // publish this thread's h writes
        __syncthreads();            // all block threads fenced
        if (tid == 0) {
            atomicAdd(&g_bar, 1u);
            unsigned target = (unsigned)(t + 1) * NB;
            while (*(volatile unsigned*)&g_bar < target) { }
            __threadfence();        // acquire; flushes L1 on sm_103a
        }
        __syncthreads();
    }

    // Final output: mean over time
    const float inv = 1.0f / (float)SS;
    *(float4*)&out[(size_t)um * HH + hb + uh] =
        make_float4(oacc[0] * inv, oacc[1] * inv, oacc[2] * inv, oacc[3] * inv);
}

// ---------------------------------------------------------------------------
// Launch: 3 graph nodes total (fixes the graph-upload memory violation)
// ---------------------------------------------------------------------------
extern "C" void kernel_launch(void* const* d_in, const int* in_sizes, int n_in,
                              void* d_out, int out_size)
{
    const float* x    = (const float*)d_in[0];
    const float* W    = (const float*)d_in[1];
    const float* U    = (const float*)d_in[2];
    const float* bias = (const float*)d_in[3];
    float* out = (float*)d_out;

    lstm_init<<<512, 256>>>();

    dim3 g1(SS * BB / 128, GG / 128);   // (512, 32)
    gemm_xw<<<g1, 256>>>(x, W, bias);

    lstm_persist<<<NB, NT>>>(U, out);
}

// round 4
// speedup vs baseline: 1.9024x; 1.9024x over previous
#include <cuda_runtime.h>
#include <math.h>
#include <stdint.h>

// Problem constants
#define BB 128      // batch
#define SS 512      // seq len
#define II 512      // input dim
#define HH 1024     // hidden dim
#define GG 4096     // 4*H (gates)

#define NB 64       // persistent CTAs for recurrence
#define NT 256      // threads per CTA (8 warps)

// ---------------------------------------------------------------------------
// Device scratch
// ---------------------------------------------------------------------------
__device__ float    g_xw[(size_t)SS * BB * GG];   // (s, b, n'=4h+g) : 1 GiB
__device__ float    g_Utr[(size_t)HH * GG];       // U  re-laid: [k][n'=4h+g], tf32
__device__ float    g_Wt[(size_t)II * GG];        // W  re-laid: [k][n'=4h+g], tf32
__device__ float    g_biasI[GG];                  // bias interleaved n'=4h+g
__device__ float    g_hbuf[2][BB * HH];           // double-buffered hidden state
__device__ unsigned g_bar;

// ---------------------------------------------------------------------------
// Helpers
// ---------------------------------------------------------------------------
__device__ __forceinline__ float sigm(float v) { return 1.0f / (1.0f + __expf(-v)); }
__device__ __forceinline__ float tf32r(float v) {
    uint32_t r;
    asm("cvt.rna.tf32.f32 %0, %1;" : "=r"(r) : "f"(v));
    return __uint_as_float(r);
}
// D = A(16x8 tf32) * B(8x8 tf32) + D  (fp32 accum), standard sm_80+ HMMA
__device__ __forceinline__ void mma_tf32(float* d, const uint32_t* a, const uint32_t* b) {
    asm volatile(
        "mma.sync.aligned.m16n8k8.row.col.f32.tf32.tf32.f32 "
        "{%0,%1,%2,%3}, {%4,%5,%6,%7}, {%8,%9}, {%0,%1,%2,%3};"
        : "+f"(d[0]), "+f"(d[1]), "+f"(d[2]), "+f"(d[3])
        : "r"(a[0]), "r"(a[1]), "r"(a[2]), "r"(a[3]), "r"(b[0]), "r"(b[1]));
}

// ---------------------------------------------------------------------------
// init: zero h buffers + barrier; build interleaved bias
// ---------------------------------------------------------------------------
__global__ void lstm_init(const float* __restrict__ bias) {
    int idx = blockIdx.x * blockDim.x + threadIdx.x; // 131072
    g_hbuf[0][idx] = 0.0f;
    g_hbuf[1][idx] = 0.0f;
    if (idx == 0) g_bar = 0u;
    if (idx < GG) {
        int h = idx >> 2, g = idx & 3;
        g_biasI[idx] = bias[g * HH + h];
    }
}

// ---------------------------------------------------------------------------
// Weight re-layout + tf32 rounding
//   g_Utr[k][4h+g] = tf32(U[k][g*1024+h])   (1024 x 4096)
//   g_Wt [k][4h+g] = tf32(W[k][g*1024+h])   ( 512 x 4096)
// ---------------------------------------------------------------------------
__global__ void ut_prep(const float* __restrict__ U) {
    size_t idx = (size_t)blockIdx.x * 256 + threadIdx.x; // 4M
    int k = (int)(idx >> 12);
    int n = (int)(idx & 4095);
    int h = n >> 2, g = n & 3;
    g_Utr[idx] = tf32r(U[(size_t)k * GG + g * HH + h]);
}
__global__ void wt_prep(const float* __restrict__ W) {
    size_t idx = (size_t)blockIdx.x * 256 + threadIdx.x; // 2M
    int k = (int)(idx >> 12);
    int n = (int)(idx & 4095);
    int h = n >> 2, g = n & 3;
    g_Wt[idx] = tf32r(W[(size_t)k * GG + g * HH + h]);
}

// ---------------------------------------------------------------------------
// GEMM 1 via mma.sync tf32: xW = x @ W + bias -> g_xw (interleaved cols)
//   M = 65536 (m = b*512+s), N = 4096 (n'), K = 512.
// CTA tile 128x128, 8 warps (2m x 4n), warp tile 64x32, K chunk 32.
// ---------------------------------------------------------------------------
#define XA_ST 36    // As stride (floats): mod32==4, 16B-aligned rows
#define XB_ST 136   // Bs stride (floats): mod32==8, 16B-aligned rows

__global__ __launch_bounds__(256) void gemm_xw_mma(const float* __restrict__ x)
{
    __shared__ float As[128 * XA_ST];   // [m][k] 18KB
    __shared__ float Bs[32 * XB_ST];    // [k][n] 17KB

    const int tid  = threadIdx.x;
    const int wid  = tid >> 5;
    const int lane = tid & 31;
    const int qr = lane >> 2;   // 0..7
    const int qc = lane & 3;    // 0..3

    const int m0 = blockIdx.x * 128;
    const int n0 = blockIdx.y * 128;
    const int m0w = (wid & 1) * 64;
    const int n0w = (wid >> 1) * 32;

    float acc[4][4][4];
#pragma unroll
    for (int i = 0; i < 4; i++)
#pragma unroll
        for (int j = 0; j < 4; j++)
#pragma unroll
            for (int q = 0; q < 4; q++) acc[i][j][q] = 0.0f;

    for (int k0 = 0; k0 < II; k0 += 32) {
        // As: 128x32 from x, tf32-rounded
#pragma unroll
        for (int i = 0; i < 4; i++) {
            int f4 = i * 256 + tid;
            int r = f4 >> 3, c4 = f4 & 7;
            float4 v = *(const float4*)&x[(size_t)(m0 + r) * II + k0 + c4 * 4];
            v.x = tf32r(v.x); v.y = tf32r(v.y); v.z = tf32r(v.z); v.w = tf32r(v.w);
            *(float4*)&As[r * XA_ST + c4 * 4] = v;
        }
        // Bs: 32x128 from g_Wt (pre-rounded)
#pragma unroll
        for (int i = 0; i < 4; i++) {
            int f4 = i * 256 + tid;
            int r = f4 >> 5, c4 = f4 & 31;
            float4 v = *(const float4*)&g_Wt[(size_t)(k0 + r) * GG + n0 + c4 * 4];
            *(float4*)&Bs[r * XB_ST + c4 * 4] = v;
        }
        __syncthreads();

#pragma unroll
        for (int kk = 0; kk < 4; kk++) {
            const int kb = kk * 8;
            uint32_t a[4][4];
#pragma unroll
            for (int mt = 0; mt < 4; mt++) {
                int mr = m0w + mt * 16;
                a[mt][0] = __float_as_uint(As[(mr + qr)     * XA_ST + kb + qc]);
                a[mt][1] = __float_as_uint(As[(mr + qr + 8) * XA_ST + kb + qc]);
                a[mt][2] = __float_as_uint(As[(mr + qr)     * XA_ST + kb + qc + 4]);
                a[mt][3] = __float_as_uint(As[(mr + qr + 8) * XA_ST + kb + qc + 4]);
            }
            uint32_t b[4][2];
#pragma unroll
            for (int nt = 0; nt < 4; nt++) {
                int nc = n0w + nt * 8 + qr;
                b[nt][0] = __float_as_uint(Bs[(kb + qc)     * XB_ST + nc]);
                b[nt][1] = __float_as_uint(Bs[(kb + qc + 4) * XB_ST + nc]);
            }
#pragma unroll
            for (int mt = 0; mt < 4; mt++)
#pragma unroll
                for (int nt = 0; nt < 4; nt++)
                    mma_tf32(acc[mt][nt], a[mt], b[nt]);
        }
        __syncthreads();
    }

    // epilogue: + biasI, scatter to g_xw[(s*BB+b)*GG + n']
#pragma unroll
    for (int nt = 0; nt < 4; nt++) {
        int col = n0 + n0w + nt * 8 + qc * 2;
        float2 bv = *(const float2*)&g_biasI[col];
#pragma unroll
        for (int mt = 0; mt < 4; mt++) {
            int r1 = m0 + m0w + mt * 16 + qr;
            int r2 = r1 + 8;
            int b1 = r1 >> 9, s1 = r1 & 511;
            int b2 = r2 >> 9, s2 = r2 & 511;
            size_t d1 = ((size_t)s1 * BB + b1) * GG + col;
            size_t d2 = ((size_t)s2 * BB + b2) * GG + col;
            *(float2*)&g_xw[d1] = make_float2(acc[mt][nt][0] + bv.x,
                                              acc[mt][nt][1] + bv.y);
            *(float2*)&g_xw[d2] = make_float2(acc[mt][nt][2] + bv.x,
                                              acc[mt][nt][3] + bv.y);
        }
    }
}

// ---------------------------------------------------------------------------
// Persistent recurrence via mma.sync tf32.
// 64 CTAs x 256 thr. CTA bx owns cols n' in [bx*64, bx*64+64)
// (= hidden units [bx*16, bx*16+16), gates interleaved).
// Per step: C[128,64] = h[128,1024] @ Utr_slice, K chunks of 64.
// Warp layout 4m x 2n -> warp tile 32x32 (2 m16 x 4 n8 tiles).
// ---------------------------------------------------------------------------
#define RA_ST 68    // As stride: mod32==4, 16B-aligned
#define RB_ST 72    // Bs stride: mod32==8, 16B-aligned
#define RS_ST 68    // staging stride
#define AS_OFF 0
#define BS_OFF (128 * RA_ST)                 // 8704
#define S_OFF  (BS_OFF + 64 * RB_ST)         // 13312
#define RSMEM_FLOATS (S_OFF + 128 * RS_ST)   // 22016 floats = 88064 B

__global__ __launch_bounds__(NT, 1) void lstm_mma(float* __restrict__ out)
{
    extern __shared__ float sm[];
    float* As = sm + AS_OFF;   // [m=128][k=64]
    float* Bs = sm + BS_OFF;   // [k=64][n=64]
    float* S  = sm + S_OFF;    // [m=128][n=64]

    const int tid  = threadIdx.x;
    const int wid  = tid >> 5;
    const int lane = tid & 31;
    const int qr = lane >> 2;
    const int qc = lane & 3;
    const int bx = blockIdx.x;

    const int m0w = (wid & 3) * 32;   // warp rows
    const int n0w = (wid >> 2) * 32;  // warp cols

    // update-phase mapping: thread -> batch row b, 8 hidden units
    const int ub   = tid >> 1;          // 0..127
    const int hoff = (tid & 1) * 8;     // 0 or 8 (within CTA's 16 units)

    float c_reg[8], oacc[8];
#pragma unroll
    for (int j = 0; j < 8; j++) { c_reg[j] = 0.f; oacc[j] = 0.f; }

    for (int t = 0; t < SS; t++) {
        const float* hcur = g_hbuf[t & 1];

        float acc[2][4][4];
#pragma unroll
        for (int i = 0; i < 2; i++)
#pragma unroll
            for (int j = 0; j < 4; j++)
#pragma unroll
                for (int q = 0; q < 4; q++) acc[i][j][q] = 0.0f;

        for (int kc = 0; kc < 16; kc++) {
            const int k0 = kc * 64;
            // As: h[0..127][k0..k0+63]  (bypass L1: cross-SM mutable)
#pragma unroll
            for (int i = 0; i < 8; i++) {
                int f4 = i * 256 + tid;
                int r = f4 >> 4, c4 = f4 & 15;
                float4 v = __ldcg((const float4*)&hcur[(size_t)r * HH + k0 + c4 * 4]);
                *(float4*)&As[r * RA_ST + c4 * 4] = v;
            }
            // Bs: Utr[k0..k0+63][bx*64..+64) (pre-rounded, read-only)
#pragma unroll
            for (int i = 0; i < 4; i++) {
                int f4 = i * 256 + tid;
                int r = f4 >> 4, c4 = f4 & 15;
                float4 v = __ldg((const float4*)&g_Utr[(size_t)(k0 + r) * GG + bx * 64 + c4 * 4]);
                *(float4*)&Bs[r * RB_ST + c4 * 4] = v;
            }
            __syncthreads();

#pragma unroll
            for (int kk = 0; kk < 8; kk++) {
                const int kb = kk * 8;
                uint32_t a[2][4];
#pragma unroll
                for (int mt = 0; mt < 2; mt++) {
                    int mr = m0w + mt * 16;
                    a[mt][0] = __float_as_uint(As[(mr + qr)     * RA_ST + kb + qc]);
                    a[mt][1] = __float_as_uint(As[(mr + qr + 8) * RA_ST + kb + qc]);
                    a[mt][2] = __float_as_uint(As[(mr + qr)     * RA_ST + kb + qc + 4]);
                    a[mt][3] = __float_as_uint(As[(mr + qr + 8) * RA_ST + kb + qc + 4]);
                }
                uint32_t b[4][2];
#pragma unroll
                for (int nt = 0; nt < 4; nt++) {
                    int nc = n0w + nt * 8 + qr;
                    b[nt][0] = __float_as_uint(Bs[(kb + qc)     * RB_ST + nc]);
                    b[nt][1] = __float_as_uint(Bs[(kb + qc + 4) * RB_ST + nc]);
                }
#pragma unroll
                for (int mt = 0; mt < 2; mt++)
#pragma unroll
                    for (int nt = 0; nt < 4; nt++)
                        mma_tf32(acc[mt][nt], a[mt], b[nt]);
            }
            __syncthreads();
        }

        // stage C -> S
#pragma unroll
        for (int mt = 0; mt < 2; mt++)
#pragma unroll
            for (int nt = 0; nt < 4; nt++) {
                int row = m0w + mt * 16 + qr;
                int col = n0w + nt * 8 + qc * 2;
                *(float2*)&S[row * RS_ST + col] =
                    make_float2(acc[mt][nt][0], acc[mt][nt][1]);
                *(float2*)&S[(row + 8) * RS_ST + col] =
                    make_float2(acc[mt][nt][2], acc[mt][nt][3]);
            }
        __syncthreads();

        // fused cell update
        {
            const float* xw = g_xw + ((size_t)t * BB + ub) * GG + bx * 64 + hoff * 4;
            const float* Sr = S + ub * RS_ST + hoff * 4;
            float hv[8];
#pragma unroll
            for (int j = 0; j < 8; j++) {
                float4 xwv = *(const float4*)&xw[j * 4];
                float4 sv  = *(const float4*)&Sr[j * 4];
                float f  = sigm(sv.x + xwv.x);
                float ii = sigm(sv.y + xwv.y);
                float g  = tanhf(sv.z + xwv.z);
                float o  = sigm(sv.w + xwv.w);
                float cc = fmaf(f, c_reg[j], ii * g);
                c_reg[j] = cc;
                float h  = o * tanhf(cc);
                oacc[j] += h;
                hv[j]    = tf32r(h);
            }
            float* hn = g_hbuf[(t + 1) & 1] + (size_t)ub * HH + bx * 16 + hoff;
            *(float4*)&hn[0] = make_float4(hv[0], hv[1], hv[2], hv[3]);
            *(float4*)&hn[4] = make_float4(hv[4], hv[5], hv[6], hv[7]);
            __threadfence();
        }

        __syncthreads();
        if (tid == 0) {
            atomicAdd(&g_bar, 1u);
            unsigned tgt = (unsigned)(t + 1) * NB;
            while (*(volatile unsigned*)&g_bar < tgt) { }
            __threadfence();
        }
        __syncthreads();
    }

    // final output: mean over time
    {
        const float inv = 1.0f / (float)SS;
        float* o = out + (size_t)ub * HH + bx * 16 + hoff;
        *(float4*)&o[0] = make_float4(oacc[0] * inv, oacc[1] * inv,
                                      oacc[2] * inv, oacc[3] * inv);
        *(float4*)&o[4] = make_float4(oacc[4] * inv, oacc[5] * inv,
                                      oacc[6] * inv, oacc[7] * inv);
    }
}

// ---------------------------------------------------------------------------
// Launch: 5 graph nodes
// ---------------------------------------------------------------------------
extern "C" void kernel_launch(void* const* d_in, const int* in_sizes, int n_in,
                              void* d_out, int out_size)
{
    const float* x    = (const float*)d_in[0];
    const float* W    = (const float*)d_in[1];
    const float* U    = (const float*)d_in[2];
    const float* bias = (const float*)d_in[3];
    float* out = (float*)d_out;

    static bool configured = false;
    if (!configured) {
        cudaFuncSetAttribute(lstm_mma,
                             cudaFuncAttributeMaxDynamicSharedMemorySize,
                             RSMEM_FLOATS * sizeof(float));
        configured = true;
    }

    lstm_init<<<512, 256>>>(bias);
    ut_prep<<<(int)(((size_t)HH * GG) / 256), 256>>>(U);
    wt_prep<<<(int)(((size_t)II * GG) / 256), 256>>>(W);

    dim3 g1(SS * BB / 128, GG / 128);   // (512, 32)
    gemm_xw_mma<<<g1, 256>>>(x);

    lstm_mma<<<NB, NT, RSMEM_FLOATS * sizeof(float)>>>(out);
}

// round 5
// speedup vs baseline: 2.2948x; 1.2062x over previous
#include <cuda_runtime.h>
#include <math.h>
#include <stdint.h>

// Problem constants
#define BB 128      // batch
#define SS 512      // seq len
#define II 512      // input dim
#define HH 1024     // hidden dim
#define GG 4096     // 4*H (gates)

#define NB 64       // persistent CTAs for recurrence
#define NT 256      // threads per CTA (8 warps)

// ---------------------------------------------------------------------------
// Device scratch
// ---------------------------------------------------------------------------
__device__ float    g_xw[(size_t)SS * BB * GG];   // (s, b, n'=4h+g) : 1 GiB
__device__ float    g_Utr[(size_t)GG * HH];       // U re-laid: [n'=4h+g][k], tf32
__device__ float    g_Wt[(size_t)II * GG];        // W re-laid: [k][n'=4h+g], tf32
__device__ float    g_biasI[GG];                  // bias interleaved n'=4h+g
__device__ float    g_hbuf[2][BB * HH];           // double-buffered hidden state
__device__ unsigned g_bar;

// ---------------------------------------------------------------------------
// Helpers
// ---------------------------------------------------------------------------
__device__ __forceinline__ float sigm(float v) { return 1.0f / (1.0f + __expf(-v)); }
__device__ __forceinline__ float tf32r(float v) {
    uint32_t r;
    asm("cvt.rna.tf32.f32 %0, %1;" : "=r"(r) : "f"(v));
    return __uint_as_float(r);
}
__device__ __forceinline__ uint32_t smem_u32(const void* p) {
    uint32_t a;
    asm("{ .reg .u64 t; cvta.to.shared.u64 t, %1; cvt.u32.u64 %0, t; }"
        : "=r"(a) : "l"(p));
    return a;
}
__device__ __forceinline__ void mma_tf32(float* d, const uint32_t* a, const uint32_t* b) {
    asm volatile(
        "mma.sync.aligned.m16n8k8.row.col.f32.tf32.tf32.f32 "
        "{%0,%1,%2,%3}, {%4,%5,%6,%7}, {%8,%9}, {%0,%1,%2,%3};"
        : "+f"(d[0]), "+f"(d[1]), "+f"(d[2]), "+f"(d[3])
        : "r"(a[0]), "r"(a[1]), "r"(a[2]), "r"(a[3]), "r"(b[0]), "r"(b[1]));
}
__device__ __forceinline__ void ldsm4(uint32_t* r, uint32_t addr) {
    asm volatile("ldmatrix.sync.aligned.m8n8.x4.shared.b16 {%0,%1,%2,%3}, [%4];"
        : "=r"(r[0]), "=r"(r[1]), "=r"(r[2]), "=r"(r[3]) : "r"(addr));
}
__device__ __forceinline__ void cp16(uint32_t s, const void* g) {
    asm volatile("cp.async.cg.shared.global [%0], [%1], 16;" :: "r"(s), "l"(g));
}
#define CP_COMMIT() asm volatile("cp.async.commit_group;" ::: "memory")
#define CP_WAIT1()  asm volatile("cp.async.wait_group 1;" ::: "memory")

// ---------------------------------------------------------------------------
// init: zero h buffers + barrier; build interleaved bias
// ---------------------------------------------------------------------------
__global__ void lstm_init(const float* __restrict__ bias) {
    int idx = blockIdx.x * blockDim.x + threadIdx.x; // 131072
    g_hbuf[0][idx] = 0.0f;
    g_hbuf[1][idx] = 0.0f;
    if (idx == 0) g_bar = 0u;
    if (idx < GG) {
        int h = idx >> 2, g = idx & 3;
        g_biasI[idx] = bias[g * HH + h];
    }
}

// ---------------------------------------------------------------------------
// Weight re-layout + tf32 rounding
//   g_Utr[n'][k] = tf32(U[k][g*1024+h]),  n'=4h+g   (4096 x 1024, n'-major)
//   g_Wt [k][n'] = tf32(W[k][g*1024+h])              ( 512 x 4096, k-major)
// ---------------------------------------------------------------------------
__global__ void ut_prep(const float* __restrict__ U) {
    size_t idx = (size_t)blockIdx.x * 256 + threadIdx.x; // 4M, idx = n'*1024 + k
    int n = (int)(idx >> 10);
    int k = (int)(idx & 1023);
    int h = n >> 2, g = n & 3;
    g_Utr[idx] = tf32r(U[(size_t)k * GG + g * HH + h]);
}
__global__ void wt_prep(const float* __restrict__ W) {
    size_t idx = (size_t)blockIdx.x * 256 + threadIdx.x; // 2M, idx = k*4096 + n'
    int k = (int)(idx >> 12);
    int n = (int)(idx & 4095);
    int h = n >> 2, g = n & 3;
    g_Wt[idx] = tf32r(W[(size_t)k * GG + g * HH + h]);
}

// ---------------------------------------------------------------------------
// GEMM 1 via mma.sync tf32 (unchanged from round 4 — passed at ~2.1ms)
// ---------------------------------------------------------------------------
#define XA_ST 36
#define XB_ST 136

__global__ __launch_bounds__(256) void gemm_xw_mma(const float* __restrict__ x)
{
    __shared__ float As[128 * XA_ST];
    __shared__ float Bs[32 * XB_ST];

    const int tid  = threadIdx.x;
    const int wid  = tid >> 5;
    const int lane = tid & 31;
    const int qr = lane >> 2;
    const int qc = lane & 3;

    const int m0 = blockIdx.x * 128;
    const int n0 = blockIdx.y * 128;
    const int m0w = (wid & 1) * 64;
    const int n0w = (wid >> 1) * 32;

    float acc[4][4][4];
#pragma unroll
    for (int i = 0; i < 4; i++)
#pragma unroll
        for (int j = 0; j < 4; j++)
#pragma unroll
            for (int q = 0; q < 4; q++) acc[i][j][q] = 0.0f;

    for (int k0 = 0; k0 < II; k0 += 32) {
#pragma unroll
        for (int i = 0; i < 4; i++) {
            int f4 = i * 256 + tid;
            int r = f4 >> 3, c4 = f4 & 7;
            float4 v = *(const float4*)&x[(size_t)(m0 + r) * II + k0 + c4 * 4];
            v.x = tf32r(v.x); v.y = tf32r(v.y); v.z = tf32r(v.z); v.w = tf32r(v.w);
            *(float4*)&As[r * XA_ST + c4 * 4] = v;
        }
#pragma unroll
        for (int i = 0; i < 4; i++) {
            int f4 = i * 256 + tid;
            int r = f4 >> 5, c4 = f4 & 31;
            float4 v = *(const float4*)&g_Wt[(size_t)(k0 + r) * GG + n0 + c4 * 4];
            *(float4*)&Bs[r * XB_ST + c4 * 4] = v;
        }
        __syncthreads();

#pragma unroll
        for (int kk = 0; kk < 4; kk++) {
            const int kb = kk * 8;
            uint32_t a[4][4];
#pragma unroll
            for (int mt = 0; mt < 4; mt++) {
                int mr = m0w + mt * 16;
                a[mt][0] = __float_as_uint(As[(mr + qr)     * XA_ST + kb + qc]);
                a[mt][1] = __float_as_uint(As[(mr + qr + 8) * XA_ST + kb + qc]);
                a[mt][2] = __float_as_uint(As[(mr + qr)     * XA_ST + kb + qc + 4]);
                a[mt][3] = __float_as_uint(As[(mr + qr + 8) * XA_ST + kb + qc + 4]);
            }
            uint32_t b[4][2];
#pragma unroll
            for (int nt = 0; nt < 4; nt++) {
                int nc = n0w + nt * 8 + qr;
                b[nt][0] = __float_as_uint(Bs[(kb + qc)     * XB_ST + nc]);
                b[nt][1] = __float_as_uint(Bs[(kb + qc + 4) * XB_ST + nc]);
            }
#pragma unroll
            for (int mt = 0; mt < 4; mt++)
#pragma unroll
                for (int nt = 0; nt < 4; nt++)
                    mma_tf32(acc[mt][nt], a[mt], b[nt]);
        }
        __syncthreads();
    }

#pragma unroll
    for (int nt = 0; nt < 4; nt++) {
        int col = n0 + n0w + nt * 8 + qc * 2;
        float2 bv = *(const float2*)&g_biasI[col];
#pragma unroll
        for (int mt = 0; mt < 4; mt++) {
            int r1 = m0 + m0w + mt * 16 + qr;
            int r2 = r1 + 8;
            int b1 = r1 >> 9, s1 = r1 & 511;
            int b2 = r2 >> 9, s2 = r2 & 511;
            size_t d1 = ((size_t)s1 * BB + b1) * GG + col;
            size_t d2 = ((size_t)s2 * BB + b2) * GG + col;
            *(float2*)&g_xw[d1] = make_float2(acc[mt][nt][0] + bv.x,
                                              acc[mt][nt][1] + bv.y);
            *(float2*)&g_xw[d2] = make_float2(acc[mt][nt][2] + bv.x,
                                              acc[mt][nt][3] + bv.y);
        }
    }
}

// ---------------------------------------------------------------------------
// Persistent recurrence: cp.async depth-3 pipeline + ldmatrix fragments.
// 64 CTAs x 256 thr. CTA bx owns cols n' in [bx*64, bx*64+64).
// Per step: C[128,64] = h[128,1024] @ Utr_slice, 16 K-chunks of 64.
// Warp layout 4m x 2n, warp tile 32x32 (2 m16 x 4 n8).
// A smem [m][k] stride 68, B smem [n][k] stride 68 (17r mod 8 distinct).
// ---------------------------------------------------------------------------
#define KC     64
#define NCHUNK 16
#define RST    68                        // floats; 272B rows, 16B aligned
#define ASZ    (128 * RST)               // 8704 floats
#define BSZ    (64 * RST)                // 4352 floats
#define STG_F  (ASZ + BSZ)               // 13056 floats per stage
#define S_OFF  (3 * STG_F)               // 39168
#define RSM_FLOATS (S_OFF + 128 * RST)   // 47872 floats = 191488 B

__global__ __launch_bounds__(NT, 1) void lstm_mma(float* __restrict__ out)
{
    extern __shared__ float sm[];
    const uint32_t sb0 = smem_u32(sm);
    float* S = sm + S_OFF;

    const int tid  = threadIdx.x;
    const int wid  = tid >> 5;
    const int lane = tid & 31;
    const int qr = lane >> 2;
    const int qc = lane & 3;
    const int bx = blockIdx.x;

    const int m0w = (wid & 3) * 32;
    const int n0w = (wid >> 2) * 32;

    // ldmatrix per-lane byte offsets (relative to stage base)
    const int rA    = lane & 15;
    const int kselA = (lane >> 4) * 4;
    const uint32_t offA0 = (uint32_t)(((m0w + rA)      * RST + kselA) * 4);
    const uint32_t offA1 = (uint32_t)(((m0w + 16 + rA) * RST + kselA) * 4);
    const int nL    = (lane & 7) | ((lane & 16) >> 1);   // 0..15
    const int kselB = (lane & 8) ? 4 : 0;
    const uint32_t offB0 = (uint32_t)((ASZ + (n0w + nL)      * RST + kselB) * 4);
    const uint32_t offB1 = (uint32_t)((ASZ + (n0w + 16 + nL) * RST + kselB) * 4);

    // cp.async per-thread piece indices (8 A pieces, 4 B pieces of 16B)
    const float* Up = g_Utr + (size_t)bx * 64 * HH;

    // update-phase mapping
    const int ub   = tid >> 1;
    const int hoff = (tid & 1) * 8;

    float c_reg[8], oacc[8];
#pragma unroll
    for (int j = 0; j < 8; j++) { c_reg[j] = 0.f; oacc[j] = 0.f; }

    for (int t = 0; t < SS; t++) {
        const float* hcur = g_hbuf[t & 1];

        // prefetch xw for the update phase (overlaps with GEMM)
        float4 xw[8];
        {
            const float4* xwp = (const float4*)(g_xw +
                ((size_t)t * BB + ub) * GG + bx * 64 + hoff * 4);
#pragma unroll
            for (int i = 0; i < 8; i++) xw[i] = __ldg(xwp + i);
        }

        float acc[2][4][4];
#pragma unroll
        for (int i = 0; i < 2; i++)
#pragma unroll
            for (int j = 0; j < 4; j++)
#pragma unroll
                for (int q = 0; q < 4; q++) acc[i][j][q] = 0.0f;

        // ---- prologue: issue chunks 0 and 1 ------------------------------
#pragma unroll
        for (int pc = 0; pc < 2; pc++) {
            uint32_t sa = sb0 + (uint32_t)(pc * STG_F * 4);
            uint32_t sbB = sa + ASZ * 4;
            int k0 = pc * KC;
#pragma unroll
            for (int i = 0; i < 8; i++) {
                int f4 = i * 256 + tid;
                int r = f4 >> 4, c4 = f4 & 15;
                cp16(sa + (uint32_t)((r * RST + c4 * 4) * 4),
                     hcur + (size_t)r * HH + k0 + c4 * 4);
            }
#pragma unroll
            for (int i = 0; i < 4; i++) {
                int f4 = i * 256 + tid;
                int r = f4 >> 4, c4 = f4 & 15;
                cp16(sbB + (uint32_t)((r * RST + c4 * 4) * 4),
                     Up + (size_t)r * HH + k0 + c4 * 4);
            }
            CP_COMMIT();
        }

        // ---- main pipeline -------------------------------------------------
        int stage = 0;      // stage of chunk kc
        int nstage = 2;     // stage for chunk kc+2
        for (int kc = 0; kc < NCHUNK; kc++) {
            CP_WAIT1();
            __syncthreads();

            // issue chunk kc+2 into nstage
            if (kc + 2 < NCHUNK) {
                uint32_t sa = sb0 + (uint32_t)(nstage * STG_F * 4);
                uint32_t sbB = sa + ASZ * 4;
                int k0 = (kc + 2) * KC;
#pragma unroll
                for (int i = 0; i < 8; i++) {
                    int f4 = i * 256 + tid;
                    int r = f4 >> 4, c4 = f4 & 15;
                    cp16(sa + (uint32_t)((r * RST + c4 * 4) * 4),
                         hcur + (size_t)r * HH + k0 + c4 * 4);
                }
#pragma unroll
                for (int i = 0; i < 4; i++) {
                    int f4 = i * 256 + tid;
                    int r = f4 >> 4, c4 = f4 & 15;
                    cp16(sbB + (uint32_t)((r * RST + c4 * 4) * 4),
                         Up + (size_t)r * HH + k0 + c4 * 4);
                }
            }
            CP_COMMIT();   // always commit (possibly empty) to keep group count

            // compute chunk kc from 'stage'
            const uint32_t su = sb0 + (uint32_t)(stage * STG_F * 4);
#pragma unroll
            for (int kk = 0; kk < 8; kk++) {
                const uint32_t kb4 = (uint32_t)(kk * 32);   // 8 floats
                uint32_t a[2][4], b[2][4];
                ldsm4(a[0], su + offA0 + kb4);
                ldsm4(a[1], su + offA1 + kb4);
                ldsm4(b[0], su + offB0 + kb4);
                ldsm4(b[1], su + offB1 + kb4);
#pragma unroll
                for (int mt = 0; mt < 2; mt++)
#pragma unroll
                    for (int nt = 0; nt < 4; nt++)
                        mma_tf32(acc[mt][nt], a[mt], &b[nt >> 1][(nt & 1) * 2]);
            }

            stage = (stage == 2) ? 0 : stage + 1;
            nstage = (nstage == 2) ? 0 : nstage + 1;
        }

        // stage C -> S
        __syncthreads();    // all MMA reads of smem done before S overwrite? S is separate region; sync for S readers below anyway
#pragma unroll
        for (int mt = 0; mt < 2; mt++)
#pragma unroll
            for (int nt = 0; nt < 4; nt++) {
                int row = m0w + mt * 16 + qr;
                int col = n0w + nt * 8 + qc * 2;
                *(float2*)&S[row * RST + col] =
                    make_float2(acc[mt][nt][0], acc[mt][nt][1]);
                *(float2*)&S[(row + 8) * RST + col] =
                    make_float2(acc[mt][nt][2], acc[mt][nt][3]);
            }
        __syncthreads();

        // fused cell update
        {
            const float* Sr = S + ub * RST + hoff * 4;
            float hv[8];
#pragma unroll
            for (int j = 0; j < 8; j++) {
                float4 sv = *(const float4*)&Sr[j * 4];
                float f  = sigm(sv.x + xw[j].x);
                float ii = sigm(sv.y + xw[j].y);
                float g  = tanhf(sv.z + xw[j].z);
                float o  = sigm(sv.w + xw[j].w);
                float cc = fmaf(f, c_reg[j], ii * g);
                c_reg[j] = cc;
                float h  = o * tanhf(cc);
                oacc[j] += h;
                hv[j]    = tf32r(h);
            }
            float* hn = g_hbuf[(t + 1) & 1] + (size_t)ub * HH + bx * 16 + hoff;
            *(float4*)&hn[0] = make_float4(hv[0], hv[1], hv[2], hv[3]);
            *(float4*)&hn[4] = make_float4(hv[4], hv[5], hv[6], hv[7]);
            __threadfence();
        }

        __syncthreads();
        if (tid == 0) {
            atomicAdd(&g_bar, 1u);
            unsigned tgt = (unsigned)(t + 1) * NB;
            while (*(volatile unsigned*)&g_bar < tgt) { }
            __threadfence();
        }
        __syncthreads();
    }

    // final output: mean over time
    {
        const float inv = 1.0f / (float)SS;
        float* o = out + (size_t)ub * HH + bx * 16 + hoff;
        *(float4*)&o[0] = make_float4(oacc[0] * inv, oacc[1] * inv,
                                      oacc[2] * inv, oacc[3] * inv);
        *(float4*)&o[4] = make_float4(oacc[4] * inv, oacc[5] * inv,
                                      oacc[6] * inv, oacc[7] * inv);
    }
}

// ---------------------------------------------------------------------------
// Launch: 5 graph nodes
// ---------------------------------------------------------------------------
extern "C" void kernel_launch(void* const* d_in, const int* in_sizes, int n_in,
                              void* d_out, int out_size)
{
    const float* x    = (const float*)d_in[0];
    const float* W    = (const float*)d_in[1];
    const float* U    = (const float*)d_in[2];
    const float* bias = (const float*)d_in[3];
    float* out = (float*)d_out;

    static bool configured = false;
    if (!configured) {
        cudaFuncSetAttribute(lstm_mma,
                             cudaFuncAttributeMaxDynamicSharedMemorySize,
                             RSM_FLOATS * sizeof(float));
        configured = true;
    }

    lstm_init<<<512, 256>>>(bias);
    ut_prep<<<(int)(((size_t)GG * HH) / 256), 256>>>(U);
    wt_prep<<<(int)(((size_t)II * GG) / 256), 256>>>(W);

    dim3 g1(SS * BB / 128, GG / 128);   // (512, 32)
    gemm_xw_mma<<<g1, 256>>>(x);

    lstm_mma<<<NB, NT, RSM_FLOATS * sizeof(float)>>>(out);
}

// round 6
// speedup vs baseline: 3.3863x; 1.4757x over previous
#include <cuda_runtime.h>
#include <cuda_fp16.h>
#include <math.h>
#include <stdint.h>

// Problem constants
#define BB 128      // batch
#define SS 512      // seq len
#define II 512      // input dim
#define HH 1024     // hidden dim
#define GG 4096     // 4*H (gates)

#define NB 64       // persistent CTAs for recurrence
#define NT 256      // threads per CTA (8 warps)

// ---------------------------------------------------------------------------
// Device scratch
// ---------------------------------------------------------------------------
__device__ float    g_xw[(size_t)SS * BB * GG];   // (s, b, n'=4h+g) : 1 GiB
__device__ __half   g_Uh[(size_t)GG * HH];        // U re-laid: [n'=4h+g][k], fp16
__device__ float    g_Wt[(size_t)II * GG];        // W re-laid: [k][n'], tf32
__device__ float    g_biasI[GG];                  // bias interleaved n'=4h+g
__device__ __half   g_hbuf[2][BB * HH];           // double-buffered hidden (fp16)
__device__ unsigned g_bar;

// ---------------------------------------------------------------------------
// Helpers
// ---------------------------------------------------------------------------
__device__ __forceinline__ float sigm(float v) { return 1.0f / (1.0f + __expf(-v)); }
__device__ __forceinline__ float tf32r(float v) {
    uint32_t r;
    asm("cvt.rna.tf32.f32 %0, %1;" : "=r"(r) : "f"(v));
    return __uint_as_float(r);
}
__device__ __forceinline__ uint32_t smem_u32(const void* p) {
    uint32_t a;
    asm("{ .reg .u64 t; cvta.to.shared.u64 t, %1; cvt.u32.u64 %0, t; }"
        : "=r"(a) : "l"(p));
    return a;
}
// tf32 mma (used by gemm_xw_mma, unchanged)
__device__ __forceinline__ void mma_tf32(float* d, const uint32_t* a, const uint32_t* b) {
    asm volatile(
        "mma.sync.aligned.m16n8k8.row.col.f32.tf32.tf32.f32 "
        "{%0,%1,%2,%3}, {%4,%5,%6,%7}, {%8,%9}, {%0,%1,%2,%3};"
        : "+f"(d[0]), "+f"(d[1]), "+f"(d[2]), "+f"(d[3])
        : "r"(a[0]), "r"(a[1]), "r"(a[2]), "r"(a[3]), "r"(b[0]), "r"(b[1]));
}
// fp16 mma, fp32 accumulate
__device__ __forceinline__ void mma_f16(float* d, const uint32_t* a, const uint32_t* b) {
    asm volatile(
        "mma.sync.aligned.m16n8k16.row.col.f32.f16.f16.f32 "
        "{%0,%1,%2,%3}, {%4,%5,%6,%7}, {%8,%9}, {%0,%1,%2,%3};"
        : "+f"(d[0]), "+f"(d[1]), "+f"(d[2]), "+f"(d[3])
        : "r"(a[0]), "r"(a[1]), "r"(a[2]), "r"(a[3]), "r"(b[0]), "r"(b[1]));
}
__device__ __forceinline__ void ldsm4(uint32_t* r, uint32_t addr) {
    asm volatile("ldmatrix.sync.aligned.m8n8.x4.shared.b16 {%0,%1,%2,%3}, [%4];"
        : "=r"(r[0]), "=r"(r[1]), "=r"(r[2]), "=r"(r[3]) : "r"(addr));
}
__device__ __forceinline__ void cp16(uint32_t s, const void* g) {
    asm volatile("cp.async.cg.shared.global [%0], [%1], 16;" :: "r"(s), "l"(g));
}
#define CP_COMMIT() asm volatile("cp.async.commit_group;" ::: "memory")
#define CP_WAIT1()  asm volatile("cp.async.wait_group 1;" ::: "memory")
#define CP_WAIT0()  asm volatile("cp.async.wait_group 0;" ::: "memory")

// ---------------------------------------------------------------------------
// init: zero h buffers (fp16, as uint32 words) + barrier; interleaved bias
// ---------------------------------------------------------------------------
__global__ void lstm_init(const float* __restrict__ bias) {
    int idx = blockIdx.x * blockDim.x + threadIdx.x; // 131072 threads
    ((uint32_t*)g_hbuf)[idx] = 0u;                   // covers both 256KB buffers
    if (idx == 0) g_bar = 0u;
    if (idx < GG) {
        int h = idx >> 2, g = idx & 3;
        g_biasI[idx] = bias[g * HH + h];
    }
}

// ---------------------------------------------------------------------------
// Weight re-layout
//   g_Uh[n'][k] = fp16(U[k][g*1024+h]),  n'=4h+g   (4096 x 1024)
//   g_Wt[k][n'] = tf32(W[k][g*1024+h])              ( 512 x 4096)
// ---------------------------------------------------------------------------
__global__ void ut_prep(const float* __restrict__ U) {
    size_t idx = (size_t)blockIdx.x * 256 + threadIdx.x; // 4M, idx = n'*1024 + k
    int n = (int)(idx >> 10);
    int k = (int)(idx & 1023);
    int h = n >> 2, g = n & 3;
    g_Uh[idx] = __float2half_rn(U[(size_t)k * GG + g * HH + h]);
}
__global__ void wt_prep(const float* __restrict__ W) {
    size_t idx = (size_t)blockIdx.x * 256 + threadIdx.x; // 2M, idx = k*4096 + n'
    int k = (int)(idx >> 12);
    int n = (int)(idx & 4095);
    int h = n >> 2, g = n & 3;
    g_Wt[idx] = tf32r(W[(size_t)k * GG + g * HH + h]);
}

// ---------------------------------------------------------------------------
// GEMM 1 via mma.sync tf32 (unchanged — ~2.1ms, proven)
// ---------------------------------------------------------------------------
#define XA_ST 36
#define XB_ST 136

__global__ __launch_bounds__(256) void gemm_xw_mma(const float* __restrict__ x)
{
    __shared__ float As[128 * XA_ST];
    __shared__ float Bs[32 * XB_ST];

    const int tid  = threadIdx.x;
    const int wid  = tid >> 5;
    const int lane = tid & 31;
    const int qr = lane >> 2;
    const int qc = lane & 3;

    const int m0 = blockIdx.x * 128;
    const int n0 = blockIdx.y * 128;
    const int m0w = (wid & 1) * 64;
    const int n0w = (wid >> 1) * 32;

    float acc[4][4][4];
#pragma unroll
    for (int i = 0; i < 4; i++)
#pragma unroll
        for (int j = 0; j < 4; j++)
#pragma unroll
            for (int q = 0; q < 4; q++) acc[i][j][q] = 0.0f;

    for (int k0 = 0; k0 < II; k0 += 32) {
#pragma unroll
        for (int i = 0; i < 4; i++) {
            int f4 = i * 256 + tid;
            int r = f4 >> 3, c4 = f4 & 7;
            float4 v = *(const float4*)&x[(size_t)(m0 + r) * II + k0 + c4 * 4];
            v.x = tf32r(v.x); v.y = tf32r(v.y); v.z = tf32r(v.z); v.w = tf32r(v.w);
            *(float4*)&As[r * XA_ST + c4 * 4] = v;
        }
#pragma unroll
        for (int i = 0; i < 4; i++) {
            int f4 = i * 256 + tid;
            int r = f4 >> 5, c4 = f4 & 31;
            float4 v = *(const float4*)&g_Wt[(size_t)(k0 + r) * GG + n0 + c4 * 4];
            *(float4*)&Bs[r * XB_ST + c4 * 4] = v;
        }
        __syncthreads();

#pragma unroll
        for (int kk = 0; kk < 4; kk++) {
            const int kb = kk * 8;
            uint32_t a[4][4];
#pragma unroll
            for (int mt = 0; mt < 4; mt++) {
                int mr = m0w + mt * 16;
                a[mt][0] = __float_as_uint(As[(mr + qr)     * XA_ST + kb + qc]);
                a[mt][1] = __float_as_uint(As[(mr + qr + 8) * XA_ST + kb + qc]);
                a[mt][2] = __float_as_uint(As[(mr + qr)     * XA_ST + kb + qc + 4]);
                a[mt][3] = __float_as_uint(As[(mr + qr + 8) * XA_ST + kb + qc + 4]);
            }
            uint32_t b[4][2];
#pragma unroll
            for (int nt = 0; nt < 4; nt++) {
                int nc = n0w + nt * 8 + qr;
                b[nt][0] = __float_as_uint(Bs[(kb + qc)     * XB_ST + nc]);
                b[nt][1] = __float_as_uint(Bs[(kb + qc + 4) * XB_ST + nc]);
            }
#pragma unroll
            for (int mt = 0; mt < 4; mt++)
#pragma unroll
                for (int nt = 0; nt < 4; nt++)
                    mma_tf32(acc[mt][nt], a[mt], b[nt]);
        }
        __syncthreads();
    }

#pragma unroll
    for (int nt = 0; nt < 4; nt++) {
        int col = n0 + n0w + nt * 8 + qc * 2;
        float2 bv = *(const float2*)&g_biasI[col];
#pragma unroll
        for (int mt = 0; mt < 4; mt++) {
            int r1 = m0 + m0w + mt * 16 + qr;
            int r2 = r1 + 8;
            int b1 = r1 >> 9, s1 = r1 & 511;
            int b2 = r2 >> 9, s2 = r2 & 511;
            size_t d1 = ((size_t)s1 * BB + b1) * GG + col;
            size_t d2 = ((size_t)s2 * BB + b2) * GG + col;
            *(float2*)&g_xw[d1] = make_float2(acc[mt][nt][0] + bv.x,
                                              acc[mt][nt][1] + bv.y);
            *(float2*)&g_xw[d2] = make_float2(acc[mt][nt][2] + bv.x,
                                              acc[mt][nt][3] + bv.y);
        }
    }
}

// ---------------------------------------------------------------------------
// Persistent recurrence: fp16 operands, U slice RESIDENT IN SMEM (loaded once),
// cp.async depth-3 pipeline for A (h), ldmatrix fragments, m16n8k16 fp16 MMA.
// 64 CTAs x 256 thr. CTA bx owns cols n' in [bx*64, bx*64+64).
// SMEM (bytes):
//   A stages : 3 x 18432  (128 rows x 144B; 64 k-halves + pad)   = 55296
//   B persist: 64 rows x 2064B (1024 k-halves + pad)             = 132096
//   S staging: 128 x 68 fp32                                     = 34816
//   total                                                        = 222208
// ---------------------------------------------------------------------------
#define KC       64                     // k per chunk (halves)
#define NCHUNK   16
#define A_RB     144                    // A row bytes (128 data + 16 pad)
#define A_STGB   (128 * A_RB)           // 18432
#define B_RB     2064                   // B row bytes (2048 data + 16 pad)
#define B_OFF    (3 * A_STGB)           // 55296
#define S_OFFB   (B_OFF + 64 * B_RB)    // 187392
#define RST      68                     // S stride (floats)
#define RSM_BYTES (S_OFFB + 128 * RST * 4)  // 222208

__global__ __launch_bounds__(NT, 1) void lstm_mma(float* __restrict__ out)
{
    extern __shared__ char smc[];
    const uint32_t sb0 = smem_u32(smc);
    float* S = (float*)(smc + S_OFFB);

    const int tid  = threadIdx.x;
    const int wid  = tid >> 5;
    const int lane = tid & 31;
    const int qr = lane >> 2;
    const int qc = lane & 3;
    const int bx = blockIdx.x;

    const int m0w = (wid & 3) * 32;   // warp rows
    const int n0w = (wid >> 2) * 32;  // warp cols

    // ldmatrix per-lane offsets
    // A (m16xk16 tile): lanes 0-7 rows m..m+7 k0; 8-15 rows m+8..15 k0;
    //                   16-23 rows m..m+7 k8(16B); 24-31 rows m+8..15 k8
    const uint32_t offA0 = (uint32_t)((m0w + (lane & 15)) * A_RB + (lane >> 4) * 16);
    const uint32_t offA1 = offA0 + 16 * A_RB;
    // B (n8xk16 tile pair): lanes 0-7 rows n..n+7 k0; 8-15 rows n..n+7 k8;
    //                       16-23 rows n+8..15 k0; 24-31 rows n+8..15 k8
    const uint32_t offB0 = (uint32_t)(B_OFF +
        (n0w + ((lane >> 4) << 3) + (lane & 7)) * B_RB + ((lane >> 3) & 1) * 16);
    const uint32_t offB1 = offB0 + 16 * B_RB;

    const __half* Up = g_Uh + (size_t)bx * 64 * HH;

    // update-phase mapping
    const int ub   = tid >> 1;          // batch row 0..127
    const int hoff = (tid & 1) * 8;     // 0 or 8

    float c_reg[8], oacc[8];
#pragma unroll
    for (int j = 0; j < 8; j++) { c_reg[j] = 0.f; oacc[j] = 0.f; }

    // ---- one-time: load U slice into persistent smem (8192 x 16B pieces) ---
#pragma unroll
    for (int i = 0; i < 32; i++) {
        int f = i * 256 + tid;
        int r = f >> 7, c = f & 127;
        cp16(sb0 + (uint32_t)(B_OFF + r * B_RB + c * 16),
             Up + (size_t)r * HH + c * 8);
    }
    CP_COMMIT();
    CP_WAIT0();
    __syncthreads();

    for (int t = 0; t < SS; t++) {
        const __half* hcur = g_hbuf[t & 1];

        // prefetch xw (fp32) for the update phase
        float4 xw[8];
        {
            const float4* xwp = (const float4*)(g_xw +
                ((size_t)t * BB + ub) * GG + bx * 64 + hoff * 4);
#pragma unroll
            for (int i = 0; i < 8; i++) xw[i] = __ldg(xwp + i);
        }

        float acc[2][4][4];
#pragma unroll
        for (int i = 0; i < 2; i++)
#pragma unroll
            for (int j = 0; j < 4; j++)
#pragma unroll
                for (int q = 0; q < 4; q++) acc[i][j][q] = 0.0f;

        // ---- prologue: A chunks 0,1 (4 cp16/thread each) -------------------
#pragma unroll
        for (int pc = 0; pc < 2; pc++) {
            uint32_t sa = sb0 + (uint32_t)(pc * A_STGB);
            int k0 = pc * KC;
#pragma unroll
            for (int i = 0; i < 4; i++) {
                int f = i * 256 + tid;
                int r = f >> 3, c = f & 7;
                cp16(sa + (uint32_t)(r * A_RB + c * 16),
                     hcur + (size_t)r * HH + k0 + c * 8);
            }
            CP_COMMIT();
        }

        // ---- main pipeline --------------------------------------------------
        int stage = 0, nstage = 2;
        for (int kc = 0; kc < NCHUNK; kc++) {
            CP_WAIT1();
            __syncthreads();

            if (kc + 2 < NCHUNK) {
                uint32_t sa = sb0 + (uint32_t)(nstage * A_STGB);
                int k0 = (kc + 2) * KC;
#pragma unroll
                for (int i = 0; i < 4; i++) {
                    int f = i * 256 + tid;
                    int r = f >> 3, c = f & 7;
                    cp16(sa + (uint32_t)(r * A_RB + c * 16),
                         hcur + (size_t)r * HH + k0 + c * 8);
                }
            }
            CP_COMMIT();   // always commit to keep group accounting

            const uint32_t su = sb0 + (uint32_t)(stage * A_STGB);
            const uint32_t kbB = sb0 + (uint32_t)(kc * 128);  // chunk k byte (B)
#pragma unroll
            for (int kk = 0; kk < 4; kk++) {
                uint32_t a[2][4], b[2][4];
                ldsm4(a[0], su + offA0 + kk * 32);
                ldsm4(a[1], su + offA1 + kk * 32);
                ldsm4(b[0], kbB + offB0 + kk * 32);
                ldsm4(b[1], kbB + offB1 + kk * 32);
#pragma unroll
                for (int mt = 0; mt < 2; mt++)
#pragma unroll
                    for (int nt = 0; nt < 4; nt++)
                        mma_f16(acc[mt][nt], a[mt], &b[nt >> 1][(nt & 1) * 2]);
            }

            stage = (stage == 2) ? 0 : stage + 1;
            nstage = (nstage == 2) ? 0 : nstage + 1;
        }

        // ---- stage C -> S ----------------------------------------------------
        __syncthreads();
#pragma unroll
        for (int mt = 0; mt < 2; mt++)
#pragma unroll
            for (int nt = 0; nt < 4; nt++) {
                int row = m0w + mt * 16 + qr;
                int col = n0w + nt * 8 + qc * 2;
                *(float2*)&S[row * RST + col] =
                    make_float2(acc[mt][nt][0], acc[mt][nt][1]);
                *(float2*)&S[(row + 8) * RST + col] =
                    make_float2(acc[mt][nt][2], acc[mt][nt][3]);
            }
        __syncthreads();

        // ---- fused cell update ----------------------------------------------
        {
            const float* Sr = S + ub * RST + hoff * 4;
            float hv[8];
#pragma unroll
            for (int j = 0; j < 8; j++) {
                float4 sv = *(const float4*)&Sr[j * 4];
                float f  = sigm(sv.x + xw[j].x);
                float ii = sigm(sv.y + xw[j].y);
                float g  = tanhf(sv.z + xw[j].z);
                float o  = sigm(sv.w + xw[j].w);
                float cc = fmaf(f, c_reg[j], ii * g);
                c_reg[j] = cc;
                float h  = o * tanhf(cc);
                oacc[j] += h;
                hv[j]    = h;
            }
            // pack 8 fp16 and store as one 16B write
            union { __half2 h2[4]; uint4 u; } pk;
            pk.h2[0] = __floats2half2_rn(hv[0], hv[1]);
            pk.h2[1] = __floats2half2_rn(hv[2], hv[3]);
            pk.h2[2] = __floats2half2_rn(hv[4], hv[5]);
            pk.h2[3] = __floats2half2_rn(hv[6], hv[7]);
            __half* hn = g_hbuf[(t + 1) & 1] + (size_t)ub * HH + bx * 16 + hoff;
            *(uint4*)hn = pk.u;
            __threadfence();
        }

        __syncthreads();
        if (tid == 0) {
            atomicAdd(&g_bar, 1u);
            unsigned tgt = (unsigned)(t + 1) * NB;
            while (*(volatile unsigned*)&g_bar < tgt) { }
            __threadfence();
        }
        __syncthreads();
    }

    // final output: mean over time
    {
        const float inv = 1.0f / (float)SS;
        float* o = out + (size_t)ub * HH + bx * 16 + hoff;
        *(float4*)&o[0] = make_float4(oacc[0] * inv, oacc[1] * inv,
                                      oacc[2] * inv, oacc[3] * inv);
        *(float4*)&o[4] = make_float4(oacc[4] * inv, oacc[5] * inv,
                                      oacc[6] * inv, oacc[7] * inv);
    }
}

// ---------------------------------------------------------------------------
// Launch: 5 graph nodes
// ---------------------------------------------------------------------------
extern "C" void kernel_launch(void* const* d_in, const int* in_sizes, int n_in,
                              void* d_out, int out_size)
{
    const float* x    = (const float*)d_in[0];
    const float* W    = (const float*)d_in[1];
    const float* U    = (const float*)d_in[2];
    const float* bias = (const float*)d_in[3];
    float* out = (float*)d_out;

    static bool configured = false;
    if (!configured) {
        cudaFuncSetAttribute(lstm_mma,
                             cudaFuncAttributeMaxDynamicSharedMemorySize,
                             RSM_BYTES);
        configured = true;
    }

    lstm_init<<<512, 256>>>(bias);
    ut_prep<<<(int)(((size_t)GG * HH) / 256), 256>>>(U);
    wt_prep<<<(int)(((size_t)II * GG) / 256), 256>>>(W);

    dim3 g1(SS * BB / 128, GG / 128);   // (512, 32)
    gemm_xw_mma<<<g1, 256>>>(x);

    lstm_mma<<<NB, NT, RSM_BYTES>>>(out);
}

// round 7
// speedup vs baseline: 4.2056x; 1.2419x over previous
#include <cuda_runtime.h>
#include <cuda_fp16.h>
#include <math.h>
#include <stdint.h>

// Problem constants
#define BB 128      // batch
#define SS 512      // seq len
#define II 512      // input dim
#define HH 1024     // hidden dim
#define GG 4096     // 4*H (gates)

#define NB 64       // persistent CTAs for recurrence
#define NT 512      // threads per CTA (16 warps)

// ---------------------------------------------------------------------------
// Device scratch
// ---------------------------------------------------------------------------
__device__ float    g_xw[(size_t)SS * BB * GG];   // (s, b, n'=4h+g) : 1 GiB
__device__ __half   g_Uh[(size_t)GG * HH];        // U re-laid: [n'][k], fp16
__device__ __half   g_Whk[(size_t)GG * II];       // W re-laid: [n'][k], fp16
__device__ __half   g_xh[(size_t)BB * SS * II];   // x in fp16, same layout
__device__ float    g_biasI[GG];                  // bias interleaved n'=4h+g
__device__ __half   g_hbuf[2][BB * HH];           // double-buffered hidden (fp16)
__device__ unsigned g_bar;

// ---------------------------------------------------------------------------
// Helpers
// ---------------------------------------------------------------------------
__device__ __forceinline__ float sigm(float v) { return 1.0f / (1.0f + __expf(-v)); }
__device__ __forceinline__ uint32_t smem_u32(const void* p) {
    uint32_t a;
    asm("{ .reg .u64 t; cvta.to.shared.u64 t, %1; cvt.u32.u64 %0, t; }"
        : "=r"(a) : "l"(p));
    return a;
}
__device__ __forceinline__ void mma_f16(float* d, const uint32_t* a, const uint32_t* b) {
    asm volatile(
        "mma.sync.aligned.m16n8k16.row.col.f32.f16.f16.f32 "
        "{%0,%1,%2,%3}, {%4,%5,%6,%7}, {%8,%9}, {%0,%1,%2,%3};"
        : "+f"(d[0]), "+f"(d[1]), "+f"(d[2]), "+f"(d[3])
        : "r"(a[0]), "r"(a[1]), "r"(a[2]), "r"(a[3]), "r"(b[0]), "r"(b[1]));
}
__device__ __forceinline__ void ldsm4(uint32_t* r, uint32_t addr) {
    asm volatile("ldmatrix.sync.aligned.m8n8.x4.shared.b16 {%0,%1,%2,%3}, [%4];"
        : "=r"(r[0]), "=r"(r[1]), "=r"(r[2]), "=r"(r[3]) : "r"(addr));
}
__device__ __forceinline__ void cp16(uint32_t s, const void* g) {
    asm volatile("cp.async.cg.shared.global [%0], [%1], 16;" :: "r"(s), "l"(g));
}
#define CP_COMMIT() asm volatile("cp.async.commit_group;" ::: "memory")
#define CP_WAIT1()  asm volatile("cp.async.wait_group 1;" ::: "memory")
#define CP_WAIT0()  asm volatile("cp.async.wait_group 0;" ::: "memory")

// ---------------------------------------------------------------------------
// init: zero h buffers + barrier; interleaved bias
// ---------------------------------------------------------------------------
__global__ void lstm_init(const float* __restrict__ bias) {
    int idx = blockIdx.x * blockDim.x + threadIdx.x; // 131072 threads
    ((uint32_t*)g_hbuf)[idx] = 0u;                   // both 256KB buffers
    if (idx == 0) g_bar = 0u;
    if (idx < GG) {
        int h = idx >> 2, g = idx & 3;
        g_biasI[idx] = bias[g * HH + h];
    }
}

// ---------------------------------------------------------------------------
// Preps: fp16 conversions / re-layouts
// ---------------------------------------------------------------------------
__global__ void ut_prep(const float* __restrict__ U) {
    size_t idx = (size_t)blockIdx.x * 256 + threadIdx.x; // 4M, idx = n'*1024+k
    int n = (int)(idx >> 10);
    int k = (int)(idx & 1023);
    int h = n >> 2, g = n & 3;
    g_Uh[idx] = __float2half_rn(U[(size_t)k * GG + g * HH + h]);
}
__global__ void wt_prep(const float* __restrict__ W) {
    size_t idx = (size_t)blockIdx.x * 256 + threadIdx.x; // 2M, idx = n'*512+k
    int n = (int)(idx >> 9);
    int k = (int)(idx & 511);
    int h = n >> 2, g = n & 3;
    g_Whk[idx] = __float2half_rn(W[(size_t)k * GG + g * HH + h]);
}
__global__ void x_prep(const float* __restrict__ x) {
    size_t i4 = (size_t)blockIdx.x * 256 + threadIdx.x; // 8.4M, 4 floats each
    float4 v = *(const float4*)(x + i4 * 4);
    __half2 a = __floats2half2_rn(v.x, v.y);
    __half2 b = __floats2half2_rn(v.z, v.w);
    *(uint2*)(g_xh + i4 * 4) = make_uint2(*(uint32_t*)&a, *(uint32_t*)&b);
}

// ---------------------------------------------------------------------------
// GEMM 1 via mma.sync fp16: xW = x @ W + bias -> g_xw (fp32, interleaved n')
//   M=65536, N=4096, K=512. CTA 128x128, K chunk 32, 8 warps (2m x 4n).
//   A smem [m][k] stride 40 halves; B smem [n][k] stride 40 halves.
// ---------------------------------------------------------------------------
#define G_RB 80     // row bytes (32 data halves + 8 pad)

__global__ __launch_bounds__(256) void gemm_xw_mma(void)
{
    __shared__ __half As[128 * 40];
    __shared__ __half Bs[128 * 40];
    const uint32_t sA = smem_u32(As);
    const uint32_t sB = smem_u32(Bs);

    const int tid  = threadIdx.x;
    const int wid  = tid >> 5;
    const int lane = tid & 31;
    const int qr = lane >> 2;
    const int qc = lane & 3;

    const int m0 = blockIdx.x * 128;
    const int n0 = blockIdx.y * 128;
    const int m0w = (wid & 1) * 64;
    const int n0w = (wid >> 1) * 32;

    // ldmatrix lane offsets
    const uint32_t offA = (uint32_t)((m0w + (lane & 15)) * G_RB + (lane >> 4) * 16);
    const uint32_t offB = (uint32_t)((n0w + ((lane >> 4) << 3) + (lane & 7)) * G_RB
                                     + ((lane >> 3) & 1) * 16);

    float acc[4][4][4];
#pragma unroll
    for (int i = 0; i < 4; i++)
#pragma unroll
        for (int j = 0; j < 4; j++)
#pragma unroll
            for (int q = 0; q < 4; q++) acc[i][j][q] = 0.0f;

    for (int k0 = 0; k0 < II; k0 += 32) {
        // As: 128 rows x 32 halves (512 x 16B, 2/thread)
#pragma unroll
        for (int i = 0; i < 2; i++) {
            int f = i * 256 + tid;
            int r = f >> 2, c = f & 3;
            *(uint4*)((char*)As + r * G_RB + c * 16) =
                *(const uint4*)&g_xh[(size_t)(m0 + r) * II + k0 + c * 8];
        }
        // Bs: 128 output-cols x 32 halves from g_Whk[n'][k]
#pragma unroll
        for (int i = 0; i < 2; i++) {
            int f = i * 256 + tid;
            int r = f >> 2, c = f & 3;
            *(uint4*)((char*)Bs + r * G_RB + c * 16) =
                *(const uint4*)&g_Whk[(size_t)(n0 + r) * II + k0 + c * 8];
        }
        __syncthreads();

#pragma unroll
        for (int kk = 0; kk < 2; kk++) {            // 2 x k16
            const uint32_t kb = kk * 32;            // bytes
            uint32_t a[4][4], b[2][4];
#pragma unroll
            for (int mt = 0; mt < 4; mt++)
                ldsm4(a[mt], sA + offA + mt * 16 * G_RB + kb);
            ldsm4(b[0], sB + offB + kb);
            ldsm4(b[1], sB + offB + 16 * G_RB + kb);
#pragma unroll
            for (int mt = 0; mt < 4; mt++)
#pragma unroll
                for (int nt = 0; nt < 4; nt++)
                    mma_f16(acc[mt][nt], a[mt], &b[nt >> 1][(nt & 1) * 2]);
        }
        __syncthreads();
    }

    // epilogue: + biasI, scatter fp32 to g_xw[(s*BB+b)*GG + n']
#pragma unroll
    for (int nt = 0; nt < 4; nt++) {
        int col = n0 + n0w + nt * 8 + qc * 2;
        float2 bv = *(const float2*)&g_biasI[col];
#pragma unroll
        for (int mt = 0; mt < 4; mt++) {
            int r1 = m0 + m0w + mt * 16 + qr;
            int r2 = r1 + 8;
            int b1 = r1 >> 9, s1 = r1 & 511;
            int b2 = r2 >> 9, s2 = r2 & 511;
            size_t d1 = ((size_t)s1 * BB + b1) * GG + col;
            size_t d2 = ((size_t)s2 * BB + b2) * GG + col;
            *(float2*)&g_xw[d1] = make_float2(acc[mt][nt][0] + bv.x,
                                              acc[mt][nt][1] + bv.y);
            *(float2*)&g_xw[d2] = make_float2(acc[mt][nt][2] + bv.x,
                                              acc[mt][nt][3] + bv.y);
        }
    }
}

// ---------------------------------------------------------------------------
// Persistent recurrence: fp16, U resident in smem, cp.async depth-3, 16 warps.
// 64 CTAs x 512 thr. CTA bx owns cols n' in [bx*64, bx*64+64).
// Warp grid 4m x 4n -> warp tile 32x16 (2 m16 x 2 n8).
// ---------------------------------------------------------------------------
#define KC       64
#define NCHUNK   16
#define A_RB     144
#define A_STGB   (128 * A_RB)           // 18432
#define B_RB     2064
#define B_OFF    (3 * A_STGB)           // 55296
#define S_OFFB   (B_OFF + 64 * B_RB)    // 187392
#define RST      68
#define RSM_BYTES (S_OFFB + 128 * RST * 4)  // 222208

__global__ __launch_bounds__(NT, 1) void lstm_mma(float* __restrict__ out)
{
    extern __shared__ char smc[];
    const uint32_t sb0 = smem_u32(smc);
    float* S = (float*)(smc + S_OFFB);

    const int tid  = threadIdx.x;
    const int wid  = tid >> 5;
    const int lane = tid & 31;
    const int qr = lane >> 2;
    const int qc = lane & 3;
    const int bx = blockIdx.x;

    const int m0w = (wid & 3) * 32;   // warp rows (0,32,64,96)
    const int n0w = (wid >> 2) * 16;  // warp cols (0,16,32,48)

    // ldmatrix lane offsets
    const uint32_t offA0 = (uint32_t)((m0w + (lane & 15)) * A_RB + (lane >> 4) * 16);
    const uint32_t offA1 = offA0 + 16 * A_RB;
    const uint32_t offB  = (uint32_t)(B_OFF +
        (n0w + ((lane >> 4) << 3) + (lane & 7)) * B_RB + ((lane >> 3) & 1) * 16);

    const __half* Up = g_Uh + (size_t)bx * 64 * HH;

    // update-phase mapping: thread -> batch row, 4 hidden units
    const int ub   = tid >> 2;          // 0..127
    const int hoff = (tid & 3) * 4;     // 0,4,8,12

    float c_reg[4], oacc[4];
#pragma unroll
    for (int j = 0; j < 4; j++) { c_reg[j] = 0.f; oacc[j] = 0.f; }

    // ---- one-time: U slice into persistent smem (8192 x 16B, 16/thread) ----
#pragma unroll
    for (int i = 0; i < 16; i++) {
        int f = i * 512 + tid;
        int r = f >> 7, c = f & 127;
        cp16(sb0 + (uint32_t)(B_OFF + r * B_RB + c * 16),
             Up + (size_t)r * HH + c * 8);
    }
    CP_COMMIT();
    CP_WAIT0();
    __syncthreads();

    for (int t = 0; t < SS; t++) {
        const __half* hcur = g_hbuf[t & 1];

        // prefetch xw (fp32) for the update phase
        float4 xw[4];
        {
            const float4* xwp = (const float4*)(g_xw +
                ((size_t)t * BB + ub) * GG + bx * 64 + hoff * 4);
#pragma unroll
            for (int i = 0; i < 4; i++) xw[i] = __ldg(xwp + i);
        }

        float acc[2][2][4];
#pragma unroll
        for (int i = 0; i < 2; i++)
#pragma unroll
            for (int j = 0; j < 2; j++)
#pragma unroll
                for (int q = 0; q < 4; q++) acc[i][j][q] = 0.0f;

        // ---- prologue: A chunks 0,1 (1024 x 16B, 2/thread each) ------------
#pragma unroll
        for (int pc = 0; pc < 2; pc++) {
            uint32_t sa = sb0 + (uint32_t)(pc * A_STGB);
            int k0 = pc * KC;
#pragma unroll
            for (int i = 0; i < 2; i++) {
                int f = i * 512 + tid;
                int r = f >> 3, c = f & 7;
                cp16(sa + (uint32_t)(r * A_RB + c * 16),
                     hcur + (size_t)r * HH + k0 + c * 8);
            }
            CP_COMMIT();
        }

        // ---- main pipeline ---------------------------------------------------
        int stage = 0, nstage = 2;
        for (int kc = 0; kc < NCHUNK; kc++) {
            CP_WAIT1();
            __syncthreads();

            if (kc + 2 < NCHUNK) {
                uint32_t sa = sb0 + (uint32_t)(nstage * A_STGB);
                int k0 = (kc + 2) * KC;
#pragma unroll
                for (int i = 0; i < 2; i++) {
                    int f = i * 512 + tid;
                    int r = f >> 3, c = f & 7;
                    cp16(sa + (uint32_t)(r * A_RB + c * 16),
                         hcur + (size_t)r * HH + k0 + c * 8);
                }
            }
            CP_COMMIT();

            const uint32_t su  = sb0 + (uint32_t)(stage * A_STGB);
            const uint32_t kbB = sb0 + (uint32_t)(kc * 128);
#pragma unroll
            for (int kk = 0; kk < 4; kk++) {
                uint32_t a[2][4], b[4];
                ldsm4(a[0], su + offA0 + kk * 32);
                ldsm4(a[1], su + offA1 + kk * 32);
                ldsm4(b,    kbB + offB + kk * 32);
#pragma unroll
                for (int mt = 0; mt < 2; mt++)
#pragma unroll
                    for (int nt = 0; nt < 2; nt++)
                        mma_f16(acc[mt][nt], a[mt], &b[nt * 2]);
            }

            stage = (stage == 2) ? 0 : stage + 1;
            nstage = (nstage == 2) ? 0 : nstage + 1;
        }

        // ---- stage C -> S ------------------------------------------------------
        __syncthreads();
#pragma unroll
        for (int mt = 0; mt < 2; mt++)
#pragma unroll
            for (int nt = 0; nt < 2; nt++) {
                int row = m0w + mt * 16 + qr;
                int col = n0w + nt * 8 + qc * 2;
                *(float2*)&S[row * RST + col] =
                    make_float2(acc[mt][nt][0], acc[mt][nt][1]);
                *(float2*)&S[(row + 8) * RST + col] =
                    make_float2(acc[mt][nt][2], acc[mt][nt][3]);
            }
        __syncthreads();

        // ---- fused cell update -------------------------------------------------
        {
            const float* Sr = S + ub * RST + hoff * 4;
            __half hv[4];
#pragma unroll
            for (int j = 0; j < 4; j++) {
                float4 sv = *(const float4*)&Sr[j * 4];
                float f  = sigm(sv.x + xw[j].x);
                float ii = sigm(sv.y + xw[j].y);
                float g  = tanhf(sv.z + xw[j].z);
                float o  = sigm(sv.w + xw[j].w);
                float cc = fmaf(f, c_reg[j], ii * g);
                c_reg[j] = cc;
                float h  = o * tanhf(cc);
                oacc[j] += h;
                hv[j]    = __float2half_rn(h);
            }
            __half* hn = g_hbuf[(t + 1) & 1] + (size_t)ub * HH + bx * 16 + hoff;
            *(uint2*)hn = *(uint2*)hv;      // 4 halves, 8B aligned
        }

        // ---- grid barrier (leader-only fences; bar.sync is cumulative) ---------
        __syncthreads();
        if (tid == 0) {
            __threadfence();                // release all CTA writes
            atomicAdd(&g_bar, 1u);
            unsigned tgt = (unsigned)(t + 1) * NB;
            while (*(volatile unsigned*)&g_bar < tgt) { }
            __threadfence();                // acquire
        }
        __syncthreads();
    }

    // final output: mean over time (4 floats = one float4 per thread)
    {
        const float inv = 1.0f / (float)SS;
        *(float4*)(out + (size_t)ub * HH + bx * 16 + hoff) =
            make_float4(oacc[0] * inv, oacc[1] * inv,
                        oacc[2] * inv, oacc[3] * inv);
    }
}

// ---------------------------------------------------------------------------
// Launch: 6 graph nodes
// ---------------------------------------------------------------------------
extern "C" void kernel_launch(void* const* d_in, const int* in_sizes, int n_in,
                              void* d_out, int out_size)
{
    const float* x    = (const float*)d_in[0];
    const float* W    = (const float*)d_in[1];
    const float* U    = (const float*)d_in[2];
    const float* bias = (const float*)d_in[3];
    float* out = (float*)d_out;

    static bool configured = false;
    if (!configured) {
        cudaFuncSetAttribute(lstm_mma,
                             cudaFuncAttributeMaxDynamicSharedMemorySize,
                             RSM_BYTES);
        configured = true;
    }

    lstm_init<<<512, 256>>>(bias);
    ut_prep<<<(int)(((size_t)GG * HH) / 256), 256>>>(U);
    wt_prep<<<(int)(((size_t)GG * II) / 256), 256>>>(W);
    x_prep<<<(int)(((size_t)BB * SS * II) / 1024), 256>>>(x);

    dim3 g1(SS * BB / 128, GG / 128);   // (512, 32)
    gemm_xw_mma<<<g1, 256>>>();

    lstm_mma<<<NB, NT, RSM_BYTES>>>(out);
}

// round 8
// speedup vs baseline: 5.8212x; 1.3842x over previous
#include <cuda_runtime.h>
#include <cuda_fp16.h>
#include <math.h>
#include <stdint.h>

// Problem constants
#define BB 128      // batch
#define SS 512      // seq len
#define II 512      // input dim
#define HH 1024     // hidden dim
#define GG 4096     // 4*H (gates)

#define NB 128      // persistent CTAs: 64 col-groups x 2 batch halves
#define NT 512      // threads per CTA (16 warps)

// ---------------------------------------------------------------------------
// Device scratch
// ---------------------------------------------------------------------------
__device__ float    g_xw[(size_t)SS * BB * GG];   // (s, b, n'=4h+g) : 1 GiB
__device__ __half   g_Uh[(size_t)GG * HH];        // U re-laid: [n'][k], fp16
__device__ __half   g_Whk[(size_t)GG * II];       // W re-laid: [n'][k], fp16
__device__ __half   g_xh[(size_t)BB * SS * II];   // x in fp16
__device__ float    g_biasI[GG];                  // bias interleaved n'=4h+g
__device__ __half   g_hbuf[2][BB * HH];           // double-buffered hidden (fp16)
__device__ unsigned g_bar;

// ---------------------------------------------------------------------------
// Helpers
// ---------------------------------------------------------------------------
__device__ __forceinline__ float sigm(float v) { return 1.0f / (1.0f + __expf(-v)); }
__device__ __forceinline__ uint32_t smem_u32(const void* p) {
    uint32_t a;
    asm("{ .reg .u64 t; cvta.to.shared.u64 t, %1; cvt.u32.u64 %0, t; }"
        : "=r"(a) : "l"(p));
    return a;
}
__device__ __forceinline__ void mma_f16(float* d, const uint32_t* a, const uint32_t* b) {
    asm volatile(
        "mma.sync.aligned.m16n8k16.row.col.f32.f16.f16.f32 "
        "{%0,%1,%2,%3}, {%4,%5,%6,%7}, {%8,%9}, {%0,%1,%2,%3};"
        : "+f"(d[0]), "+f"(d[1]), "+f"(d[2]), "+f"(d[3])
        : "r"(a[0]), "r"(a[1]), "r"(a[2]), "r"(a[3]), "r"(b[0]), "r"(b[1]));
}
__device__ __forceinline__ void ldsm4(uint32_t* r, uint32_t addr) {
    asm volatile("ldmatrix.sync.aligned.m8n8.x4.shared.b16 {%0,%1,%2,%3}, [%4];"
        : "=r"(r[0]), "=r"(r[1]), "=r"(r[2]), "=r"(r[3]) : "r"(addr));
}
__device__ __forceinline__ void cp16(uint32_t s, const void* g) {
    asm volatile("cp.async.cg.shared.global [%0], [%1], 16;" :: "r"(s), "l"(g));
}
#define CP_COMMIT() asm volatile("cp.async.commit_group;" ::: "memory")
#define CP_WAIT1()  asm volatile("cp.async.wait_group 1;" ::: "memory")
#define CP_WAIT0()  asm volatile("cp.async.wait_group 0;" ::: "memory")

// ---------------------------------------------------------------------------
// init: zero h buffers + barrier; interleaved bias
// ---------------------------------------------------------------------------
__global__ void lstm_init(const float* __restrict__ bias) {
    int idx = blockIdx.x * blockDim.x + threadIdx.x; // 131072 threads
    ((uint32_t*)g_hbuf)[idx] = 0u;                   // both 256KB buffers
    if (idx == 0) g_bar = 0u;
    if (idx < GG) {
        int h = idx >> 2, g = idx & 3;
        g_biasI[idx] = bias[g * HH + h];
    }
}

// ---------------------------------------------------------------------------
// Preps: fp16 conversions / re-layouts
// ---------------------------------------------------------------------------
__global__ void ut_prep(const float* __restrict__ U) {
    size_t idx = (size_t)blockIdx.x * 256 + threadIdx.x; // 4M, idx = n'*1024+k
    int n = (int)(idx >> 10);
    int k = (int)(idx & 1023);
    int h = n >> 2, g = n & 3;
    g_Uh[idx] = __float2half_rn(U[(size_t)k * GG + g * HH + h]);
}
__global__ void wt_prep(const float* __restrict__ W) {
    size_t idx = (size_t)blockIdx.x * 256 + threadIdx.x; // 2M, idx = n'*512+k
    int n = (int)(idx >> 9);
    int k = (int)(idx & 511);
    int h = n >> 2, g = n & 3;
    g_Whk[idx] = __float2half_rn(W[(size_t)k * GG + g * HH + h]);
}
__global__ void x_prep(const float* __restrict__ x) {
    size_t i4 = (size_t)blockIdx.x * 256 + threadIdx.x; // 8.4M, 4 floats each
    float4 v = *(const float4*)(x + i4 * 4);
    __half2 a = __floats2half2_rn(v.x, v.y);
    __half2 b = __floats2half2_rn(v.z, v.w);
    *(uint2*)(g_xh + i4 * 4) = make_uint2(*(uint32_t*)&a, *(uint32_t*)&b);
}

// ---------------------------------------------------------------------------
// GEMM 1 via mma.sync fp16 (unchanged from round 7 — proven)
// ---------------------------------------------------------------------------
#define G_RB 80     // row bytes (32 data halves + 8 pad)

__global__ __launch_bounds__(256) void gemm_xw_mma(void)
{
    __shared__ __half As[128 * 40];
    __shared__ __half Bs[128 * 40];
    const uint32_t sA = smem_u32(As);
    const uint32_t sB = smem_u32(Bs);

    const int tid  = threadIdx.x;
    const int wid  = tid >> 5;
    const int lane = tid & 31;
    const int qr = lane >> 2;
    const int qc = lane & 3;

    const int m0 = blockIdx.x * 128;
    const int n0 = blockIdx.y * 128;
    const int m0w = (wid & 1) * 64;
    const int n0w = (wid >> 1) * 32;

    const uint32_t offA = (uint32_t)((m0w + (lane & 15)) * G_RB + (lane >> 4) * 16);
    const uint32_t offB = (uint32_t)((n0w + ((lane >> 4) << 3) + (lane & 7)) * G_RB
                                     + ((lane >> 3) & 1) * 16);

    float acc[4][4][4];
#pragma unroll
    for (int i = 0; i < 4; i++)
#pragma unroll
        for (int j = 0; j < 4; j++)
#pragma unroll
            for (int q = 0; q < 4; q++) acc[i][j][q] = 0.0f;

    for (int k0 = 0; k0 < II; k0 += 32) {
#pragma unroll
        for (int i = 0; i < 2; i++) {
            int f = i * 256 + tid;
            int r = f >> 2, c = f & 3;
            *(uint4*)((char*)As + r * G_RB + c * 16) =
                *(const uint4*)&g_xh[(size_t)(m0 + r) * II + k0 + c * 8];
        }
#pragma unroll
        for (int i = 0; i < 2; i++) {
            int f = i * 256 + tid;
            int r = f >> 2, c = f & 3;
            *(uint4*)((char*)Bs + r * G_RB + c * 16) =
                *(const uint4*)&g_Whk[(size_t)(n0 + r) * II + k0 + c * 8];
        }
        __syncthreads();

#pragma unroll
        for (int kk = 0; kk < 2; kk++) {
            const uint32_t kb = kk * 32;
            uint32_t a[4][4], b[2][4];
#pragma unroll
            for (int mt = 0; mt < 4; mt++)
                ldsm4(a[mt], sA + offA + mt * 16 * G_RB + kb);
            ldsm4(b[0], sB + offB + kb);
            ldsm4(b[1], sB + offB + 16 * G_RB + kb);
#pragma unroll
            for (int mt = 0; mt < 4; mt++)
#pragma unroll
                for (int nt = 0; nt < 4; nt++)
                    mma_f16(acc[mt][nt], a[mt], &b[nt >> 1][(nt & 1) * 2]);
        }
        __syncthreads();
    }

#pragma unroll
    for (int nt = 0; nt < 4; nt++) {
        int col = n0 + n0w + nt * 8 + qc * 2;
        float2 bv = *(const float2*)&g_biasI[col];
#pragma unroll
        for (int mt = 0; mt < 4; mt++) {
            int r1 = m0 + m0w + mt * 16 + qr;
            int r2 = r1 + 8;
            int b1 = r1 >> 9, s1 = r1 & 511;
            int b2 = r2 >> 9, s2 = r2 & 511;
            size_t d1 = ((size_t)s1 * BB + b1) * GG + col;
            size_t d2 = ((size_t)s2 * BB + b2) * GG + col;
            *(float2*)&g_xw[d1] = make_float2(acc[mt][nt][0] + bv.x,
                                              acc[mt][nt][1] + bv.y);
            *(float2*)&g_xw[d2] = make_float2(acc[mt][nt][2] + bv.x,
                                              acc[mt][nt][3] + bv.y);
        }
    }
}

// ---------------------------------------------------------------------------
// Persistent recurrence: 128 CTAs (64 col-groups x 2 batch halves), 16 warps.
// CTA bx: cx = bx>>1 owns cols n' in [cx*64, cx*64+64);
//         mh = bx&1 owns batch rows [mh*64, mh*64+64).
// U slice resident in smem. KC=128 halves per chunk, 8 chunks, depth-3 cp.async.
// Warp grid 4m x 4n -> warp tile 16x16 (1 A-ldsm4 + 1 B-ldsm4 + 2 MMA per kk).
// ---------------------------------------------------------------------------
#define KC       128
#define NCHUNK   8
#define A_RB     272                    // 64 rows x (256 data + 16 pad) bytes
#define A_STGB   (64 * A_RB)            // 17408
#define B_RB     2064
#define B_OFF    (3 * A_STGB)           // 52224
#define S_OFFB   (B_OFF + 64 * B_RB)    // 184320
#define RST      68
#define RSM_BYTES (S_OFFB + 64 * RST * 4)   // 201728

__global__ __launch_bounds__(NT, 1) void lstm_mma(float* __restrict__ out)
{
    extern __shared__ char smc[];
    const uint32_t sb0 = smem_u32(smc);
    float* S = (float*)(smc + S_OFFB);

    const int tid  = threadIdx.x;
    const int wid  = tid >> 5;
    const int lane = tid & 31;
    const int qr = lane >> 2;
    const int qc = lane & 3;
    const int cx = blockIdx.x >> 1;     // column group 0..63
    const int mh = blockIdx.x & 1;      // batch half 0..1

    const int m0w = (wid & 3) * 16;     // warp rows (0,16,32,48)
    const int n0w = (wid >> 2) * 16;    // warp cols (0,16,32,48)

    // ldmatrix lane offsets
    const uint32_t offA = (uint32_t)((m0w + (lane & 15)) * A_RB + (lane >> 4) * 16);
    const uint32_t offB = (uint32_t)(B_OFF +
        (n0w + ((lane >> 4) << 3) + (lane & 7)) * B_RB + ((lane >> 3) & 1) * 16);

    const __half* Up = g_Uh + (size_t)cx * 64 * HH;
    const int mrow0 = mh * 64;          // first batch row

    // update-phase mapping: thread -> batch row, 2 hidden units
    const int ub   = tid >> 3;          // 0..63 (local batch row)
    const int hof  = (tid & 7) * 2;     // local hidden unit 0..14 (2 per thread)

    float c_reg[2], oacc[2];
    c_reg[0] = c_reg[1] = oacc[0] = oacc[1] = 0.f;

    // ---- one-time: U slice into persistent smem (8192 x 16B, 16/thread) ----
#pragma unroll
    for (int i = 0; i < 16; i++) {
        int f = i * 512 + tid;
        int r = f >> 7, c = f & 127;
        cp16(sb0 + (uint32_t)(B_OFF + r * B_RB + c * 16),
             Up + (size_t)r * HH + c * 8);
    }
    CP_COMMIT();
    CP_WAIT0();
    __syncthreads();

    for (int t = 0; t < SS; t++) {
        const __half* hcur = g_hbuf[t & 1] + (size_t)mrow0 * HH;

        // prefetch xw (fp32) for the update phase: 2 float4 per thread
        float4 xw0, xw1;
        {
            const float* xwp = g_xw + ((size_t)t * BB + mrow0 + ub) * GG
                             + cx * 64 + hof * 4;
            xw0 = __ldg((const float4*)xwp);
            xw1 = __ldg((const float4*)(xwp + 4));
        }

        float acc[2][4];
#pragma unroll
        for (int j = 0; j < 2; j++)
#pragma unroll
            for (int q = 0; q < 4; q++) acc[j][q] = 0.0f;

        // ---- prologue: A chunks 0,1 (1024 x 16B, 2/thread each) -------------
#pragma unroll
        for (int pc = 0; pc < 2; pc++) {
            uint32_t sa = sb0 + (uint32_t)(pc * A_STGB);
            int k0 = pc * KC;
#pragma unroll
            for (int i = 0; i < 2; i++) {
                int f = i * 512 + tid;
                int r = f >> 4, c = f & 15;
                cp16(sa + (uint32_t)(r * A_RB + c * 16),
                     hcur + (size_t)r * HH + k0 + c * 8);
            }
            CP_COMMIT();
        }

        // ---- main pipeline ----------------------------------------------------
        int stage = 0, nstage = 2;
        for (int kc = 0; kc < NCHUNK; kc++) {
            CP_WAIT1();
            __syncthreads();

            if (kc + 2 < NCHUNK) {
                uint32_t sa = sb0 + (uint32_t)(nstage * A_STGB);
                int k0 = (kc + 2) * KC;
#pragma unroll
                for (int i = 0; i < 2; i++) {
                    int f = i * 512 + tid;
                    int r = f >> 4, c = f & 15;
                    cp16(sa + (uint32_t)(r * A_RB + c * 16),
                         hcur + (size_t)r * HH + k0 + c * 8);
                }
            }
            CP_COMMIT();

            const uint32_t su  = sb0 + (uint32_t)(stage * A_STGB);
            const uint32_t kbB = (uint32_t)(kc * 256);     // B chunk byte offset
#pragma unroll
            for (int kk = 0; kk < 8; kk++) {
                uint32_t a[4], b[4];
                ldsm4(a, su + offA + kk * 32);
                ldsm4(b, sb0 + offB + kbB + kk * 32);
#pragma unroll
                for (int nt = 0; nt < 2; nt++)
                    mma_f16(acc[nt], a, &b[nt * 2]);
            }

            stage = (stage == 2) ? 0 : stage + 1;
            nstage = (nstage == 2) ? 0 : nstage + 1;
        }

        // ---- stage C -> S --------------------------------------------------------
        __syncthreads();
#pragma unroll
        for (int nt = 0; nt < 2; nt++) {
            int row = m0w + qr;
            int col = n0w + nt * 8 + qc * 2;
            *(float2*)&S[row * RST + col] = make_float2(acc[nt][0], acc[nt][1]);
            *(float2*)&S[(row + 8) * RST + col] = make_float2(acc[nt][2], acc[nt][3]);
        }
        __syncthreads();

        // ---- fused cell update ----------------------------------------------------
        {
            const float* Sr = S + ub * RST + hof * 4;
            float4 sv0 = *(const float4*)&Sr[0];
            float4 sv1 = *(const float4*)&Sr[4];
            __half hv[2];
            {
                float f  = sigm(sv0.x + xw0.x);
                float ii = sigm(sv0.y + xw0.y);
                float g  = tanhf(sv0.z + xw0.z);
                float o  = sigm(sv0.w + xw0.w);
                float cc = fmaf(f, c_reg[0], ii * g);
                c_reg[0] = cc;
                float h  = o * tanhf(cc);
                oacc[0] += h;
                hv[0]    = __float2half_rn(h);
            }
            {
                float f  = sigm(sv1.x + xw1.x);
                float ii = sigm(sv1.y + xw1.y);
                float g  = tanhf(sv1.z + xw1.z);
                float o  = sigm(sv1.w + xw1.w);
                float cc = fmaf(f, c_reg[1], ii * g);
                c_reg[1] = cc;
                float h  = o * tanhf(cc);
                oacc[1] += h;
                hv[1]    = __float2half_rn(h);
            }
            __half* hn = g_hbuf[(t + 1) & 1]
                       + (size_t)(mrow0 + ub) * HH + cx * 16 + hof;
            *(uint32_t*)hn = *(uint32_t*)hv;    // 2 halves, 4B aligned
        }

        // ---- grid barrier (leader-only fences; bar.sync is cumulative) -----------
        __syncthreads();
        if (tid == 0) {
            __threadfence();                // release all CTA writes
            atomicAdd(&g_bar, 1u);
            unsigned tgt = (unsigned)(t + 1) * NB;
            while (*(volatile unsigned*)&g_bar < tgt) { }
            __threadfence();                // acquire
        }
        __syncthreads();
    }

    // final output: mean over time (2 floats per thread)
    {
        const float inv = 1.0f / (float)SS;
        *(float2*)(out + (size_t)(mrow0 + ub) * HH + cx * 16 + hof) =
            make_float2(oacc[0] * inv, oacc[1] * inv);
    }
}

// ---------------------------------------------------------------------------
// Launch: 6 graph nodes
// ---------------------------------------------------------------------------
extern "C" void kernel_launch(void* const* d_in, const int* in_sizes, int n_in,
                              void* d_out, int out_size)
{
    const float* x    = (const float*)d_in[0];
    const float* W    = (const float*)d_in[1];
    const float* U    = (const float*)d_in[2];
    const float* bias = (const float*)d_in[3];
    float* out = (float*)d_out;

    static bool configured = false;
    if (!configured) {
        cudaFuncSetAttribute(lstm_mma,
                             cudaFuncAttributeMaxDynamicSharedMemorySize,
                             RSM_BYTES);
        configured = true;
    }

    lstm_init<<<512, 256>>>(bias);
    ut_prep<<<(int)(((size_t)GG * HH) / 256), 256>>>(U);
    wt_prep<<<(int)(((size_t)GG * II) / 256), 256>>>(W);
    x_prep<<<(int)(((size_t)BB * SS * II) / 1024), 256>>>(x);

    dim3 g1(SS * BB / 128, GG / 128);   // (512, 32)
    gemm_xw_mma<<<g1, 256>>>();

    lstm_mma<<<NB, NT, RSM_BYTES>>>(out);
}